// round 1
// baseline (speedup 1.0000x reference)
#include <cuda_runtime.h>

// Problem dims (fixed by the reference)
#define BB 16
#define CC 256
#define NPIX 4096   // H*W

// ---------------- scratch (device globals; no allocations allowed) ----------
__device__ float g_G[BB * CC * CC];   // x x^T per batch
__device__ float g_T[BB * CC * CC];   // Wq G
__device__ float g_L[BB * CC * CC];   // logits -> softmax A (in place)
__device__ float g_M[BB * CC * CC];   // A Wv
__device__ float g_sx[BB * CC];       // row sums of x
__device__ float g_qs[BB * CC];       // Wq sx
__device__ float g_ks[BB * CC];       // Wk sx
__device__ float g_cv[BB * CC];       // A bv

// ---------------- row sums: sx[b][c] = sum_n x[b][c][n] ---------------------
__global__ void rowsum_kernel(const float* __restrict__ x) {
    int row = blockIdx.x * 8 + (threadIdx.x >> 5);  // 16*256 = 4096 rows
    int lane = threadIdx.x & 31;
    const float* p = x + (size_t)row * NPIX;
    float s = 0.f;
    for (int i = lane; i < NPIX; i += 32) s += p[i];
#pragma unroll
    for (int o = 16; o; o >>= 1) s += __shfl_xor_sync(0xFFFFFFFFu, s, o);
    if (lane == 0) g_sx[row] = s;
}

// ---------------- generic 64x64 tiled SGEMM -------------------------------
// A: [M,K] row-major (lda=K). B: TRANSB ? [N,K] (ldb=K) : [K,N] (ldb=Ncols).
// C: [M,Ncols]. Batched via strides (stride 0 => shared operand).
template <bool TRANSB>
__global__ void gemm64(const float* __restrict__ Ag, const float* __restrict__ Bg,
                       float* __restrict__ Cg, int K, int Ncols,
                       long sA, long sB, long sC) {
    __shared__ float As[16][68];
    __shared__ float Bs[16][68];
    int b = blockIdx.z;
    const float* A = Ag + (size_t)b * sA + (size_t)(blockIdx.y * 64) * K;
    const float* B;
    if (TRANSB) B = Bg + (size_t)b * sB + (size_t)(blockIdx.x * 64) * K;
    else        B = Bg + (size_t)b * sB + blockIdx.x * 64;
    float* C = Cg + (size_t)b * sC + (size_t)(blockIdx.y * 64) * Ncols + blockIdx.x * 64;

    int tid = threadIdx.x;
    int tx = tid & 15, ty = tid >> 4;
    float acc[4][4] = {};

    for (int k0 = 0; k0 < K; k0 += 16) {
#pragma unroll
        for (int p = 0; p < 4; p++) {                  // A tile: (row, k) mapping
            int idx = tid + p * 256;
            int r = idx >> 4, kk = idx & 15;
            As[kk][r] = A[(size_t)r * K + k0 + kk];
        }
        if (TRANSB) {
#pragma unroll
            for (int p = 0; p < 4; p++) {
                int idx = tid + p * 256;
                int r = idx >> 4, kk = idx & 15;
                Bs[kk][r] = B[(size_t)r * K + k0 + kk];
            }
        } else {
#pragma unroll
            for (int p = 0; p < 4; p++) {
                int idx = tid + p * 256;
                int kk = idx >> 6, n = idx & 63;
                Bs[kk][n] = B[(size_t)(k0 + kk) * Ncols + n];
            }
        }
        __syncthreads();
#pragma unroll
        for (int kk = 0; kk < 16; kk++) {
            float4 av = *(const float4*)&As[kk][ty * 4];
            float4 bv = *(const float4*)&Bs[kk][tx * 4];
            float a[4] = {av.x, av.y, av.z, av.w};
            float c4[4] = {bv.x, bv.y, bv.z, bv.w};
#pragma unroll
            for (int i = 0; i < 4; i++)
#pragma unroll
                for (int j = 0; j < 4; j++) acc[i][j] += a[i] * c4[j];
        }
        __syncthreads();
    }
#pragma unroll
    for (int i = 0; i < 4; i++)
#pragma unroll
        for (int j = 0; j < 4; j++)
            C[(size_t)(ty * 4 + i) * Ncols + tx * 4 + j] = acc[i][j];
}

// ---------------- qs = Wq sx, ks = Wk sx (per batch) ------------------------
__global__ void proj_sums(const float* __restrict__ wq, const float* __restrict__ wk) {
    int b = blockIdx.x;
    int o = threadIdx.x;
    const float* sx = g_sx + b * CC;
    float s1 = 0.f, s2 = 0.f;
    const float* rq = wq + o * CC;
    const float* rk = wk + o * CC;
    for (int c = 0; c < CC; c++) {
        float sv = sx[c];
        s1 += rq[c] * sv;
        s2 += rk[c] * sv;
    }
    g_qs[b * CC + o] = s1;
    g_ks[b * CC + o] = s2;
}

// ---------------- softmax over logits (adds rank-1 bias terms, scales) ------
__global__ void softmax_kernel(const float* __restrict__ bq, const float* __restrict__ bk) {
    int row = blockIdx.x;          // 0..4095 == b*256 + c
    int b = row >> 8, c = row & 255;
    int d = threadIdx.x;
    __shared__ float red[256];

    float v = g_L[(size_t)row * CC + d];
    float bqc = bq[c];
    v += g_qs[b * CC + c] * bk[d] + bqc * g_ks[b * CC + d] + 4096.f * bqc * bk[d];
    v *= 0.0625f;  // 1/sqrt(256)

    red[d] = v;
    __syncthreads();
#pragma unroll
    for (int s = 128; s; s >>= 1) {
        if (d < s) red[d] = fmaxf(red[d], red[d + s]);
        __syncthreads();
    }
    float m = red[0];
    __syncthreads();
    float e = __expf(v - m);
    red[d] = e;
    __syncthreads();
#pragma unroll
    for (int s = 128; s; s >>= 1) {
        if (d < s) red[d] += red[d + s];
        __syncthreads();
    }
    g_L[(size_t)row * CC + d] = e * (1.0f / red[0]);
}

// ---------------- cv = A bv --------------------------------------------------
__global__ void cvec_kernel(const float* __restrict__ bv) {
    int b = blockIdx.x;
    int c = threadIdx.x;
    const float* arow = g_L + (size_t)(b * CC + c) * CC;
    float s = 0.f;
    for (int d = 0; d < CC; d++) s += arow[d] * bv[d];
    g_cv[b * CC + c] = s;
}

// ---------------- stage C: out = x + M x + cv 1^T ---------------------------
__global__ void stagec_kernel(const float* __restrict__ x, float* __restrict__ out) {
    __shared__ float As[16][68];
    __shared__ float Bs[16][68];
    int b = blockIdx.z;
    const float* A = g_M + (size_t)b * CC * CC + (size_t)(blockIdx.y * 64) * CC;
    const float* B = x + (size_t)b * CC * NPIX + blockIdx.x * 64;

    int tid = threadIdx.x;
    int tx = tid & 15, ty = tid >> 4;
    float acc[4][4] = {};

    for (int k0 = 0; k0 < CC; k0 += 16) {
#pragma unroll
        for (int p = 0; p < 4; p++) {
            int idx = tid + p * 256;
            int r = idx >> 4, kk = idx & 15;
            As[kk][r] = A[(size_t)r * CC + k0 + kk];
        }
#pragma unroll
        for (int p = 0; p < 4; p++) {
            int idx = tid + p * 256;
            int kk = idx >> 6, n = idx & 63;
            Bs[kk][n] = B[(size_t)(k0 + kk) * NPIX + n];
        }
        __syncthreads();
#pragma unroll
        for (int kk = 0; kk < 16; kk++) {
            float4 av = *(const float4*)&As[kk][ty * 4];
            float4 bv = *(const float4*)&Bs[kk][tx * 4];
            float a[4] = {av.x, av.y, av.z, av.w};
            float c4[4] = {bv.x, bv.y, bv.z, bv.w};
#pragma unroll
            for (int i = 0; i < 4; i++)
#pragma unroll
                for (int j = 0; j < 4; j++) acc[i][j] += a[i] * c4[j];
        }
        __syncthreads();
    }
#pragma unroll
    for (int i = 0; i < 4; i++) {
        int row = blockIdx.y * 64 + ty * 4 + i;
        float cv = g_cv[b * CC + row];
#pragma unroll
        for (int j = 0; j < 4; j++) {
            int col = blockIdx.x * 64 + tx * 4 + j;
            size_t idx = (size_t)b * CC * NPIX + (size_t)row * NPIX + col;
            out[idx] = x[idx] + acc[i][j] + cv;
        }
    }
}

// ---------------- launcher ---------------------------------------------------
extern "C" void kernel_launch(void* const* d_in, const int* in_sizes, int n_in,
                              void* d_out, int out_size) {
    const float* x  = (const float*)d_in[0];
    const float* wq = (const float*)d_in[1];
    const float* bq = (const float*)d_in[2];
    const float* wk = (const float*)d_in[3];
    const float* bk = (const float*)d_in[4];
    const float* wv = (const float*)d_in[5];
    const float* bv = (const float*)d_in[6];
    float* out = (float*)d_out;

    float *pG, *pT, *pL, *pM;
    cudaGetSymbolAddress((void**)&pG, g_G);
    cudaGetSymbolAddress((void**)&pT, g_T);
    cudaGetSymbolAddress((void**)&pL, g_L);
    cudaGetSymbolAddress((void**)&pM, g_M);

    const long CN = (long)CC * NPIX;   // batch stride of x
    const long C2 = (long)CC * CC;     // batch stride of 256x256 mats

    // sx[b][c]
    rowsum_kernel<<<512, 256>>>(x);
    // G = x x^T   (A=x, B=x transposed; K=4096)
    gemm64<true><<<dim3(4, 4, 16), 256>>>(x, x, pG, NPIX, CC, CN, CN, C2);
    // qs = Wq sx, ks = Wk sx
    proj_sums<<<16, 256>>>(wq, wk);
    // T = Wq G   (K=256)
    gemm64<false><<<dim3(4, 4, 16), 256>>>(wq, pG, pT, CC, CC, 0, C2, C2);
    // L = T Wk^T
    gemm64<true><<<dim3(4, 4, 16), 256>>>(pT, wk, pL, CC, CC, C2, 0, C2);
    // A = softmax((L + rank-1 bias terms) / 16)   [in place]
    softmax_kernel<<<4096, 256>>>(bq, bk);
    // M = A Wv
    gemm64<false><<<dim3(4, 4, 16), 256>>>(pL, wv, pM, CC, CC, C2, 0, C2);
    // cv = A bv
    cvec_kernel<<<16, 256>>>(bv);
    // out = x + M x + cv
    stagec_kernel<<<dim3(64, 4, 16), 256>>>(x, out);
}

// round 4
// speedup vs baseline: 1.1452x; 1.1452x over previous
#include <cuda_runtime.h>
#include <cuda_bf16.h>

#define BB 16
#define CC 256
#define NPIX 4096
typedef __nv_bfloat16 bf16;
typedef unsigned int u32;

__device__ float g_G[BB * CC * CC];
__device__ float g_T[BB * CC * CC];
__device__ float g_L[BB * CC * CC];
__device__ float g_M[BB * CC * CC];
__device__ float g_Wvt[CC * CC];
__device__ float g_sx[BB * CC], g_qs[BB * CC], g_ks[BB * CC], g_cv[BB * CC];

// ---------------- helpers ----------------
__device__ __forceinline__ void split2(float f, bf16& h, bf16& l) {
    h = __float2bfloat16(f);
    l = __float2bfloat16(f - __bfloat162float(h));
}
__device__ __forceinline__ u32 pack2(bf16 a, bf16 b) {
    return (u32)__bfloat16_as_ushort(a) | ((u32)__bfloat16_as_ushort(b) << 16);
}
__device__ __forceinline__ void cvt4(float4 v, uint2& h, uint2& l) {
    bf16 h0, l0, h1, l1, h2, l2, h3, l3;
    split2(v.x, h0, l0); split2(v.y, h1, l1);
    split2(v.z, h2, l2); split2(v.w, h3, l3);
    h = make_uint2(pack2(h0, h1), pack2(h2, h3));
    l = make_uint2(pack2(l0, l1), pack2(l2, l3));
}
__device__ __forceinline__ void mma16816(float* c, const u32* a, const u32* b) {
    asm volatile(
        "mma.sync.aligned.m16n8k16.row.col.f32.bf16.bf16.f32 "
        "{%0,%1,%2,%3}, {%4,%5,%6,%7}, {%8,%9}, {%0,%1,%2,%3};"
        : "+f"(c[0]), "+f"(c[1]), "+f"(c[2]), "+f"(c[3])
        : "r"(a[0]), "r"(a[1]), "r"(a[2]), "r"(a[3]), "r"(b[0]), "r"(b[1]));
}

// ---------------- unified hi/lo mma.sync GEMM ----------------
// C[128,128] tile: A fp32 [M,K] K-major. B: BTRANS ? [K,N] : [N,K].
// EPI 0: store fp32 C (ldc=256). EPI 1: out = x + D + cv (ld=4096).
template <int BTRANS, int EPI>
__global__ void __launch_bounds__(256, 1) mgemm(
    const float* __restrict__ A, const float* __restrict__ B, float* __restrict__ C,
    int K, int lda, int ldb, long sA, long sB, long sC,
    const float* __restrict__ xres, const float* __restrict__ cvv, float* __restrict__ outp)
{
    __shared__ __align__(16) unsigned short Ah[128][40], Al[128][40];
    __shared__ __align__(16) unsigned short Bh[128][40], Bl[128][40];

    int tid = threadIdx.x, lane = tid & 31, wid = tid >> 5;
    int wm = wid >> 2, wn = wid & 3;
    int bx = blockIdx.x, by = blockIdx.y, b = blockIdx.z;
    const float* Ab = A + (size_t)b * sA + (size_t)(by * 128) * lda;
    const float* Bb = B + (size_t)b * sB;

    float acc[4][4][4] = {};
    float4 va[4], vb[4];

    int arow = tid >> 1, acb = (tid & 1) * 16;      // A / non-trans B mapping
    int trow = tid >> 3, tcb = (tid & 7) * 16;      // BTRANS mapping

    auto LDG = [&](int k0) {
#pragma unroll
        for (int j = 0; j < 4; j++)
            va[j] = *(const float4*)(Ab + (size_t)arow * lda + k0 + acb + 4 * j);
        if (BTRANS) {
#pragma unroll
            for (int j = 0; j < 4; j++)
                vb[j] = *(const float4*)(Bb + (size_t)(k0 + trow) * ldb + bx * 128 + tcb + 4 * j);
        } else {
#pragma unroll
            for (int j = 0; j < 4; j++)
                vb[j] = *(const float4*)(Bb + (size_t)(bx * 128 + arow) * ldb + k0 + acb + 4 * j);
        }
    };
    auto STS = [&]() {
#pragma unroll
        for (int j = 0; j < 4; j++) {
            uint2 h, l;
            cvt4(va[j], h, l);
            *(uint2*)&Ah[arow][acb + 4 * j] = h;
            *(uint2*)&Al[arow][acb + 4 * j] = l;
        }
        if (BTRANS) {
#pragma unroll
            for (int j = 0; j < 4; j++) {
                float4 v = vb[j];
                bf16 h0, l0, h1, l1, h2, l2, h3, l3;
                split2(v.x, h0, l0); split2(v.y, h1, l1);
                split2(v.z, h2, l2); split2(v.w, h3, l3);
                int c0 = tcb + 4 * j;
                Bh[c0 + 0][trow] = __bfloat16_as_ushort(h0);
                Bh[c0 + 1][trow] = __bfloat16_as_ushort(h1);
                Bh[c0 + 2][trow] = __bfloat16_as_ushort(h2);
                Bh[c0 + 3][trow] = __bfloat16_as_ushort(h3);
                Bl[c0 + 0][trow] = __bfloat16_as_ushort(l0);
                Bl[c0 + 1][trow] = __bfloat16_as_ushort(l1);
                Bl[c0 + 2][trow] = __bfloat16_as_ushort(l2);
                Bl[c0 + 3][trow] = __bfloat16_as_ushort(l3);
            }
        } else {
#pragma unroll
            for (int j = 0; j < 4; j++) {
                uint2 h, l;
                cvt4(vb[j], h, l);
                *(uint2*)&Bh[arow][acb + 4 * j] = h;
                *(uint2*)&Bl[arow][acb + 4 * j] = l;
            }
        }
    };

    int T = K >> 5;
    LDG(0);
    for (int t = 0; t < T; t++) {
        STS();
        __syncthreads();
        if (t + 1 < T) LDG((t + 1) << 5);
#pragma unroll
        for (int kc = 0; kc < 32; kc += 16) {
            int kk = kc + (lane & 3) * 2;
            u32 afh[4][4], afl[4][4], bfh[4][2], bfl[4][2];
#pragma unroll
            for (int mf = 0; mf < 4; mf++) {
                int r0 = wm * 64 + mf * 16 + (lane >> 2);
                afh[mf][0] = *(const u32*)&Ah[r0][kk];
                afh[mf][1] = *(const u32*)&Ah[r0 + 8][kk];
                afh[mf][2] = *(const u32*)&Ah[r0][kk + 8];
                afh[mf][3] = *(const u32*)&Ah[r0 + 8][kk + 8];
                afl[mf][0] = *(const u32*)&Al[r0][kk];
                afl[mf][1] = *(const u32*)&Al[r0 + 8][kk];
                afl[mf][2] = *(const u32*)&Al[r0][kk + 8];
                afl[mf][3] = *(const u32*)&Al[r0 + 8][kk + 8];
            }
#pragma unroll
            for (int nf = 0; nf < 4; nf++) {
                int c0 = wn * 32 + nf * 8 + (lane >> 2);
                bfh[nf][0] = *(const u32*)&Bh[c0][kk];
                bfh[nf][1] = *(const u32*)&Bh[c0][kk + 8];
                bfl[nf][0] = *(const u32*)&Bl[c0][kk];
                bfl[nf][1] = *(const u32*)&Bl[c0][kk + 8];
            }
#pragma unroll
            for (int mf = 0; mf < 4; mf++)
#pragma unroll
                for (int nf = 0; nf < 4; nf++) {
                    mma16816(acc[mf][nf], afh[mf], bfh[nf]);
                    mma16816(acc[mf][nf], afh[mf], bfl[nf]);
                    mma16816(acc[mf][nf], afl[mf], bfh[nf]);
                }
        }
        __syncthreads();
    }

    // ---------------- epilogue ----------------
#pragma unroll
    for (int mf = 0; mf < 4; mf++) {
        int rloc = wm * 64 + mf * 16 + (lane >> 2);
        int rg = by * 128 + rloc;
#pragma unroll
        for (int nf = 0; nf < 4; nf++) {
            int cg = bx * 128 + wn * 32 + nf * 8 + (lane & 3) * 2;
            float* a = acc[mf][nf];
            if (EPI == 0) {
                float* p = C + (size_t)b * sC + (size_t)rg * CC + cg;
                *(float2*)p = make_float2(a[0], a[1]);
                *(float2*)(p + 8 * CC) = make_float2(a[2], a[3]);
            } else {
                size_t o0 = (size_t)b * CC * NPIX + (size_t)rg * NPIX + cg;
                size_t o1 = o0 + 8 * NPIX;
                float cv0 = cvv[b * CC + rg];
                float cv1 = cvv[b * CC + rg + 8];
                float2 x0 = *(const float2*)(xres + o0);
                float2 x1 = *(const float2*)(xres + o1);
                *(float2*)(outp + o0) = make_float2(x0.x + a[0] + cv0, x0.y + a[1] + cv0);
                *(float2*)(outp + o1) = make_float2(x1.x + a[2] + cv1, x1.y + a[3] + cv1);
            }
        }
    }
}

// ---------------- small helpers ----------------
__global__ void rowsum_kernel(const float* __restrict__ x) {
    int row = blockIdx.x * 8 + (threadIdx.x >> 5);
    int lane = threadIdx.x & 31;
    const float* p = x + (size_t)row * NPIX;
    float s = 0.f;
    for (int i = lane; i < NPIX; i += 32) s += p[i];
#pragma unroll
    for (int o = 16; o; o >>= 1) s += __shfl_xor_sync(0xFFFFFFFFu, s, o);
    if (lane == 0) g_sx[row] = s;
}
__global__ void wvt_kernel(const float* __restrict__ wv) {
    int d = blockIdx.x, e = threadIdx.x;
    g_Wvt[e * CC + d] = wv[d * CC + e];
}
__global__ void proj_sums(const float* __restrict__ wq, const float* __restrict__ wk) {
    int b = blockIdx.x, o = threadIdx.x;
    const float* sx = g_sx + b * CC;
    float s1 = 0.f, s2 = 0.f;
    const float* rq = wq + o * CC;
    const float* rk = wk + o * CC;
    for (int c = 0; c < CC; c++) { float sv = sx[c]; s1 += rq[c] * sv; s2 += rk[c] * sv; }
    g_qs[b * CC + o] = s1;
    g_ks[b * CC + o] = s2;
}
__global__ void softmax_kernel(const float* __restrict__ bq, const float* __restrict__ bk) {
    int row = blockIdx.x;
    int b = row >> 8, c = row & 255;
    int d = threadIdx.x;
    __shared__ float red[256];
    float v = g_L[(size_t)row * CC + d];
    float bqc = bq[c];
    v += g_qs[b * CC + c] * bk[d] + bqc * g_ks[b * CC + d] + 4096.f * bqc * bk[d];
    v *= 0.0625f;
    red[d] = v;
    __syncthreads();
#pragma unroll
    for (int s = 128; s; s >>= 1) { if (d < s) red[d] = fmaxf(red[d], red[d + s]); __syncthreads(); }
    float m = red[0];
    __syncthreads();
    float e = __expf(v - m);
    red[d] = e;
    __syncthreads();
#pragma unroll
    for (int s = 128; s; s >>= 1) { if (d < s) red[d] += red[d + s]; __syncthreads(); }
    g_L[(size_t)row * CC + d] = e * (1.0f / red[0]);
}
__global__ void cvec_kernel(const float* __restrict__ bv) {
    int b = blockIdx.x, c = threadIdx.x;
    const float* ar = g_L + (size_t)(b * CC + c) * CC;
    float s = 0.f;
    for (int d = 0; d < CC; d++) s += ar[d] * bv[d];
    g_cv[b * CC + c] = s;
}

// ---------------- launcher ----------------
extern "C" void kernel_launch(void* const* d_in, const int* in_sizes, int n_in,
                              void* d_out, int out_size) {
    const float* x  = (const float*)d_in[0];
    const float* wq = (const float*)d_in[1];
    const float* bq = (const float*)d_in[2];
    const float* wk = (const float*)d_in[3];
    const float* bk = (const float*)d_in[4];
    const float* wv = (const float*)d_in[5];
    const float* bv = (const float*)d_in[6];
    float* out = (float*)d_out;

    float *pG, *pT, *pL, *pM, *pWvt, *pcv;
    cudaGetSymbolAddress((void**)&pG, g_G);
    cudaGetSymbolAddress((void**)&pT, g_T);
    cudaGetSymbolAddress((void**)&pL, g_L);
    cudaGetSymbolAddress((void**)&pM, g_M);
    cudaGetSymbolAddress((void**)&pWvt, g_Wvt);
    cudaGetSymbolAddress((void**)&pcv, g_cv);

    const long CN = (long)CC * NPIX;
    const long C2 = (long)CC * CC;

    rowsum_kernel<<<512, 256>>>(x);
    wvt_kernel<<<256, 256>>>(wv);
    proj_sums<<<16, 256>>>(wq, wk);
    // G = x x^T  (both operands K-major rows of x, K=4096)
    mgemm<0, 0><<<dim3(2, 2, 16), 256>>>(x, x, pG, NPIX, NPIX, NPIX, CN, CN, C2,
                                         nullptr, nullptr, nullptr);
    // T = Wq G   (G symmetric -> B[n][k] = G row-major)
    mgemm<0, 0><<<dim3(2, 2, 16), 256>>>(wq, pG, pT, CC, CC, CC, 0, C2, C2,
                                         nullptr, nullptr, nullptr);
    // L = T Wk^T (B[n=d][k=c] = Wk row-major)
    mgemm<0, 0><<<dim3(2, 2, 16), 256>>>(pT, wk, pL, CC, CC, CC, C2, 0, C2,
                                         nullptr, nullptr, nullptr);
    softmax_kernel<<<4096, 256>>>(bq, bk);
    // M = A Wv   (B[n=e][k=d] = Wv^T, pre-transposed)
    mgemm<0, 0><<<dim3(2, 2, 16), 256>>>(pL, pWvt, pM, CC, CC, CC, C2, 0, C2,
                                         nullptr, nullptr, nullptr);
    cvec_kernel<<<16, 256>>>(bv);
    // out = x + M x + cv   (B = x [K=d, N=n] -> BTRANS)
    mgemm<1, 1><<<dim3(32, 2, 16), 256>>>(pM, x, nullptr, CC, CC, NPIX, C2, CN, 0,
                                          x, pcv, out);
}

// round 6
// speedup vs baseline: 1.5733x; 1.3738x over previous
#include <cuda_runtime.h>
#include <cuda_bf16.h>

#define BB 16
#define CC 256
#define NPIX 4096
typedef __nv_bfloat16 bf16;
typedef unsigned int u32;
typedef unsigned short u16;

// ---------------- scratch (device globals) ----------------
__device__ float g_G[BB * CC * CC];
__device__ float g_Gp[2 * BB * CC * CC];
__device__ float g_T[BB * CC * CC];
__device__ float g_L[BB * CC * CC];
__device__ float g_M[BB * CC * CC];
__device__ float g_Wvt[CC * CC];
__device__ float g_sx[BB * CC], g_qs[BB * CC], g_ks[BB * CC], g_cv[BB * CC];
__device__ __align__(16) bf16 g_xth[(size_t)BB * NPIX * CC];
__device__ __align__(16) bf16 g_xtl[(size_t)BB * NPIX * CC];
__device__ __align__(16) bf16 g_Mh[BB * CC * CC];
__device__ __align__(16) bf16 g_Ml[BB * CC * CC];

// ---------------- helpers ----------------
__device__ __forceinline__ void split2(float f, bf16& h, bf16& l) {
    h = __float2bfloat16(f);
    l = __float2bfloat16(f - __bfloat162float(h));
}
__device__ __forceinline__ u32 pack2(bf16 a, bf16 b) {
    return (u32)__bfloat16_as_ushort(a) | ((u32)__bfloat16_as_ushort(b) << 16);
}
__device__ __forceinline__ void cvt4(float4 v, uint2& h, uint2& l) {
    bf16 h0, l0, h1, l1, h2, l2, h3, l3;
    split2(v.x, h0, l0); split2(v.y, h1, l1);
    split2(v.z, h2, l2); split2(v.w, h3, l3);
    h = make_uint2(pack2(h0, h1), pack2(h2, h3));
    l = make_uint2(pack2(l0, l1), pack2(l2, l3));
}
__device__ __forceinline__ void mma16816(float* c, const u32* a, const u32* b) {
    asm volatile(
        "mma.sync.aligned.m16n8k16.row.col.f32.bf16.bf16.f32 "
        "{%0,%1,%2,%3}, {%4,%5,%6,%7}, {%8,%9}, {%0,%1,%2,%3};"
        : "+f"(c[0]), "+f"(c[1]), "+f"(c[2]), "+f"(c[3])
        : "r"(a[0]), "r"(a[1]), "r"(a[2]), "r"(a[3]), "r"(b[0]), "r"(b[1]));
}

// ---------------- fp32-input hi/lo mma GEMM (proven R4 core + split-K) ------
// b = z & bmask; kbase = (z >> sb) * kps. C stored at z*sC (partials when split).
__global__ void __launch_bounds__(256, 1) mgemm(
    const float* __restrict__ A, const float* __restrict__ B, float* __restrict__ C,
    int K, int lda, int ldb, long sA, long sB, long sC,
    int bmask, int sb, int kps)
{
    __shared__ __align__(16) u16 Ah[128][40], Al[128][40];
    __shared__ __align__(16) u16 Bh[128][40], Bl[128][40];
    int tid = threadIdx.x, lane = tid & 31, wid = tid >> 5;
    int wm = wid >> 2, wn = wid & 3;
    int bx = blockIdx.x, by = blockIdx.y, z = blockIdx.z;
    int b = z & bmask;
    int kbase = (z >> sb) * kps;
    const float* Ab = A + (size_t)b * sA + (size_t)(by * 128) * lda + kbase;
    const float* Bb = B + (size_t)b * sB + kbase;
    float acc[4][4][4] = {};
    float4 va[4], vb[4];
    int arow = tid >> 1, acb = (tid & 1) * 16;
    auto LDG = [&](int k0) {
#pragma unroll
        for (int j = 0; j < 4; j++) {
            va[j] = *(const float4*)(Ab + (size_t)arow * lda + k0 + acb + 4 * j);
            vb[j] = *(const float4*)(Bb + (size_t)(bx * 128 + arow) * ldb + k0 + acb + 4 * j);
        }
    };
    auto STS = [&]() {
#pragma unroll
        for (int j = 0; j < 4; j++) {
            uint2 h, l;
            cvt4(va[j], h, l);
            *(uint2*)&Ah[arow][acb + 4 * j] = h;
            *(uint2*)&Al[arow][acb + 4 * j] = l;
            cvt4(vb[j], h, l);
            *(uint2*)&Bh[arow][acb + 4 * j] = h;
            *(uint2*)&Bl[arow][acb + 4 * j] = l;
        }
    };
    int T = K >> 5;
    LDG(0);
    for (int t = 0; t < T; t++) {
        STS();
        __syncthreads();
        if (t + 1 < T) LDG((t + 1) << 5);
#pragma unroll
        for (int kc = 0; kc < 32; kc += 16) {
            int kk = kc + (lane & 3) * 2;
            u32 afh[4][4], afl[4][4], bfh[4][2], bfl[4][2];
#pragma unroll
            for (int mf = 0; mf < 4; mf++) {
                int r0 = wm * 64 + mf * 16 + (lane >> 2);
                afh[mf][0] = *(const u32*)&Ah[r0][kk];
                afh[mf][1] = *(const u32*)&Ah[r0 + 8][kk];
                afh[mf][2] = *(const u32*)&Ah[r0][kk + 8];
                afh[mf][3] = *(const u32*)&Ah[r0 + 8][kk + 8];
                afl[mf][0] = *(const u32*)&Al[r0][kk];
                afl[mf][1] = *(const u32*)&Al[r0 + 8][kk];
                afl[mf][2] = *(const u32*)&Al[r0][kk + 8];
                afl[mf][3] = *(const u32*)&Al[r0 + 8][kk + 8];
            }
#pragma unroll
            for (int nf = 0; nf < 4; nf++) {
                int c0 = wn * 32 + nf * 8 + (lane >> 2);
                bfh[nf][0] = *(const u32*)&Bh[c0][kk];
                bfh[nf][1] = *(const u32*)&Bh[c0][kk + 8];
                bfl[nf][0] = *(const u32*)&Bl[c0][kk];
                bfl[nf][1] = *(const u32*)&Bl[c0][kk + 8];
            }
#pragma unroll
            for (int mf = 0; mf < 4; mf++)
#pragma unroll
                for (int nf = 0; nf < 4; nf++) {
                    mma16816(acc[mf][nf], afh[mf], bfh[nf]);
                    mma16816(acc[mf][nf], afh[mf], bfl[nf]);
                    mma16816(acc[mf][nf], afl[mf], bfh[nf]);
                }
        }
        __syncthreads();
    }
#pragma unroll
    for (int mf = 0; mf < 4; mf++) {
        int rg = by * 128 + wm * 64 + mf * 16 + (lane >> 2);
#pragma unroll
        for (int nf = 0; nf < 4; nf++) {
            int cg = bx * 128 + wn * 32 + nf * 8 + (lane & 3) * 2;
            float* a = acc[mf][nf];
            float* p = C + (size_t)z * sC + (size_t)rg * CC + cg;
            *(float2*)p = make_float2(a[0], a[1]);
            *(float2*)(p + 8 * CC) = make_float2(a[2], a[3]);
        }
    }
}

// ---------------- bf16-input stage C GEMM: out = x + M x + cv ---------------
__global__ void __launch_bounds__(256, 1) cgemm(
    const bf16* __restrict__ Ahg, const bf16* __restrict__ Alg,
    const bf16* __restrict__ Bhg, const bf16* __restrict__ Blg,
    const float* __restrict__ xres, const float* __restrict__ cvv,
    float* __restrict__ outp)
{
    __shared__ __align__(16) u16 Ah[128][40], Al[128][40];
    __shared__ __align__(16) u16 Bh[128][40], Bl[128][40];
    int tid = threadIdx.x, lane = tid & 31, wid = tid >> 5;
    int wm = wid >> 2, wn = wid & 3;
    int bx = blockIdx.x, by = blockIdx.y, b = blockIdx.z;
    const bf16* Abh = Ahg + (size_t)b * CC * CC + (size_t)(by * 128) * CC;
    const bf16* Abl = Alg + (size_t)b * CC * CC + (size_t)(by * 128) * CC;
    const bf16* Bbh = Bhg + (size_t)b * NPIX * CC + (size_t)(bx * 128) * CC;
    const bf16* Bbl = Blg + (size_t)b * NPIX * CC + (size_t)(bx * 128) * CC;
    float acc[4][4][4] = {};
    uint4 rah[2], ral[2], rbh[2], rbl[2];
    int arow = tid >> 1, acb = (tid & 1) * 16;
    auto LDG = [&](int k0) {
#pragma unroll
        for (int j = 0; j < 2; j++) {
            rah[j] = *(const uint4*)(Abh + (size_t)arow * CC + k0 + acb + 8 * j);
            ral[j] = *(const uint4*)(Abl + (size_t)arow * CC + k0 + acb + 8 * j);
            rbh[j] = *(const uint4*)(Bbh + (size_t)arow * CC + k0 + acb + 8 * j);
            rbl[j] = *(const uint4*)(Bbl + (size_t)arow * CC + k0 + acb + 8 * j);
        }
    };
    LDG(0);
    for (int t = 0; t < 8; t++) {
#pragma unroll
        for (int j = 0; j < 2; j++) {
            *(uint4*)&Ah[arow][acb + 8 * j] = rah[j];
            *(uint4*)&Al[arow][acb + 8 * j] = ral[j];
            *(uint4*)&Bh[arow][acb + 8 * j] = rbh[j];
            *(uint4*)&Bl[arow][acb + 8 * j] = rbl[j];
        }
        __syncthreads();
        if (t + 1 < 8) LDG((t + 1) << 5);
#pragma unroll
        for (int kc = 0; kc < 32; kc += 16) {
            int kk = kc + (lane & 3) * 2;
            u32 afh[4][4], afl[4][4], bfh[4][2], bfl[4][2];
#pragma unroll
            for (int mf = 0; mf < 4; mf++) {
                int r0 = wm * 64 + mf * 16 + (lane >> 2);
                afh[mf][0] = *(const u32*)&Ah[r0][kk];
                afh[mf][1] = *(const u32*)&Ah[r0 + 8][kk];
                afh[mf][2] = *(const u32*)&Ah[r0][kk + 8];
                afh[mf][3] = *(const u32*)&Ah[r0 + 8][kk + 8];
                afl[mf][0] = *(const u32*)&Al[r0][kk];
                afl[mf][1] = *(const u32*)&Al[r0 + 8][kk];
                afl[mf][2] = *(const u32*)&Al[r0][kk + 8];
                afl[mf][3] = *(const u32*)&Al[r0 + 8][kk + 8];
            }
#pragma unroll
            for (int nf = 0; nf < 4; nf++) {
                int c0 = wn * 32 + nf * 8 + (lane >> 2);
                bfh[nf][0] = *(const u32*)&Bh[c0][kk];
                bfh[nf][1] = *(const u32*)&Bh[c0][kk + 8];
                bfl[nf][0] = *(const u32*)&Bl[c0][kk];
                bfl[nf][1] = *(const u32*)&Bl[c0][kk + 8];
            }
#pragma unroll
            for (int mf = 0; mf < 4; mf++)
#pragma unroll
                for (int nf = 0; nf < 4; nf++) {
                    mma16816(acc[mf][nf], afh[mf], bfh[nf]);
                    mma16816(acc[mf][nf], afh[mf], bfl[nf]);
                    mma16816(acc[mf][nf], afl[mf], bfh[nf]);
                }
        }
        __syncthreads();
    }
#pragma unroll
    for (int mf = 0; mf < 4; mf++) {
        int rg = by * 128 + wm * 64 + mf * 16 + (lane >> 2);
#pragma unroll
        for (int nf = 0; nf < 4; nf++) {
            int cg = bx * 128 + wn * 32 + nf * 8 + (lane & 3) * 2;
            float* a = acc[mf][nf];
            size_t o0 = (size_t)b * CC * NPIX + (size_t)rg * NPIX + cg;
            size_t o1 = o0 + 8 * NPIX;
            float cv0 = cvv[b * CC + rg];
            float cv1 = cvv[b * CC + rg + 8];
            float2 x0 = *(const float2*)(xres + o0);
            float2 x1 = *(const float2*)(xres + o1);
            *(float2*)(outp + o0) = make_float2(x0.x + a[0] + cv0, x0.y + a[1] + cv0);
            *(float2*)(outp + o1) = make_float2(x1.x + a[2] + cv1, x1.y + a[3] + cv1);
        }
    }
}

// ---------------- split + transpose x -> xth/xtl ----------------
__global__ void splitx_kernel(const float* __restrict__ x) {
    __shared__ u32 st[32][33];
    int b = blockIdx.z, c0 = blockIdx.y * 32, n0 = blockIdx.x * 32;
    int tid = threadIdx.x;
    int c = tid >> 3, n4 = (tid & 7) * 4;
    float4 v = *(const float4*)(x + ((size_t)(b * CC + c0 + c)) * NPIX + n0 + n4);
    bf16 h[4], l[4];
    split2(v.x, h[0], l[0]); split2(v.y, h[1], l[1]);
    split2(v.z, h[2], l[2]); split2(v.w, h[3], l[3]);
#pragma unroll
    for (int j = 0; j < 4; j++)
        st[c][n4 + j] = (u32)__bfloat16_as_ushort(h[j]) | ((u32)__bfloat16_as_ushort(l[j]) << 16);
    __syncthreads();
    int n = tid >> 3, c4 = (tid & 7) * 4;
    bf16 th[4], tl[4];
#pragma unroll
    for (int j = 0; j < 4; j++) {
        u32 w = st[c4 + j][n];
        th[j] = __ushort_as_bfloat16((u16)(w & 0xFFFF));
        tl[j] = __ushort_as_bfloat16((u16)(w >> 16));
    }
    size_t to = ((size_t)b * NPIX + n0 + n) * CC + c0 + c4;
    *(uint2*)(g_xth + to) = make_uint2(pack2(th[0], th[1]), pack2(th[2], th[3]));
    *(uint2*)(g_xtl + to) = make_uint2(pack2(tl[0], tl[1]), pack2(tl[2], tl[3]));
}

// ---------------- split M ----------------
__global__ void splitm_kernel() {
    int i = (blockIdx.x * 256 + threadIdx.x) * 4;
    float4 v = *(const float4*)(g_M + i);
    bf16 h[4], l[4];
    split2(v.x, h[0], l[0]); split2(v.y, h[1], l[1]);
    split2(v.z, h[2], l[2]); split2(v.w, h[3], l[3]);
    *(uint2*)(g_Mh + i) = make_uint2(pack2(h[0], h[1]), pack2(h[2], h[3]));
    *(uint2*)(g_Ml + i) = make_uint2(pack2(l[0], l[1]), pack2(l[2], l[3]));
}

// ---------------- reduce G partials (split-K 2) ----------------
__global__ void reduceg_kernel() {
    int i = (blockIdx.x * 256 + threadIdx.x) * 4;
    float4 a = *(const float4*)(g_Gp + i);
    float4 b = *(const float4*)(g_Gp + BB * CC * CC + i);
    *(float4*)(g_G + i) = make_float4(a.x + b.x, a.y + b.y, a.z + b.z, a.w + b.w);
}

// ---------------- small helpers ----------------
__global__ void rowsum_kernel(const float* __restrict__ x) {
    int row = blockIdx.x * 8 + (threadIdx.x >> 5);
    int lane = threadIdx.x & 31;
    const float* p = x + (size_t)row * NPIX;
    float s = 0.f;
    for (int i = lane; i < NPIX; i += 32) s += p[i];
#pragma unroll
    for (int o = 16; o; o >>= 1) s += __shfl_xor_sync(0xFFFFFFFFu, s, o);
    if (lane == 0) g_sx[row] = s;
}
__global__ void wvt_kernel(const float* __restrict__ wv) {
    int d = blockIdx.x, e = threadIdx.x;
    g_Wvt[e * CC + d] = wv[d * CC + e];
}
__global__ void proj_sums(const float* __restrict__ wq, const float* __restrict__ wk) {
    int b = blockIdx.x, o = threadIdx.x;
    const float* sx = g_sx + b * CC;
    float s1 = 0.f, s2 = 0.f;
    const float* rq = wq + o * CC;
    const float* rk = wk + o * CC;
    for (int c = 0; c < CC; c++) { float sv = sx[c]; s1 += rq[c] * sv; s2 += rk[c] * sv; }
    g_qs[b * CC + o] = s1;
    g_ks[b * CC + o] = s2;
}
__global__ void softmax_kernel(const float* __restrict__ bq, const float* __restrict__ bk) {
    int row = blockIdx.x;
    int b = row >> 8, c = row & 255;
    int d = threadIdx.x;
    __shared__ float red[256];
    float v = g_L[(size_t)row * CC + d];
    float bqc = bq[c];
    v += g_qs[b * CC + c] * bk[d] + bqc * g_ks[b * CC + d] + 4096.f * bqc * bk[d];
    v *= 0.0625f;
    red[d] = v;
    __syncthreads();
#pragma unroll
    for (int s = 128; s; s >>= 1) { if (d < s) red[d] = fmaxf(red[d], red[d + s]); __syncthreads(); }
    float m = red[0];
    __syncthreads();
    float e = __expf(v - m);
    red[d] = e;
    __syncthreads();
#pragma unroll
    for (int s = 128; s; s >>= 1) { if (d < s) red[d] += red[d + s]; __syncthreads(); }
    g_L[(size_t)row * CC + d] = e * (1.0f / red[0]);
}
__global__ void cvec_kernel(const float* __restrict__ bv) {
    int b = blockIdx.x, c = threadIdx.x;
    const float* ar = g_L + (size_t)(b * CC + c) * CC;
    float s = 0.f;
    for (int d = 0; d < CC; d++) s += ar[d] * bv[d];
    g_cv[b * CC + c] = s;
}

// ---------------- launcher ----------------
extern "C" void kernel_launch(void* const* d_in, const int* in_sizes, int n_in,
                              void* d_out, int out_size) {
    const float* x  = (const float*)d_in[0];
    const float* wq = (const float*)d_in[1];
    const float* bq = (const float*)d_in[2];
    const float* wk = (const float*)d_in[3];
    const float* bk = (const float*)d_in[4];
    const float* wv = (const float*)d_in[5];
    const float* bv = (const float*)d_in[6];
    float* out = (float*)d_out;

    float *pG, *pGp, *pT, *pL, *pM, *pWvt, *pcv;
    bf16 *pxth, *pxtl, *pMh, *pMl;
    cudaGetSymbolAddress((void**)&pG, g_G);
    cudaGetSymbolAddress((void**)&pGp, g_Gp);
    cudaGetSymbolAddress((void**)&pT, g_T);
    cudaGetSymbolAddress((void**)&pL, g_L);
    cudaGetSymbolAddress((void**)&pM, g_M);
    cudaGetSymbolAddress((void**)&pWvt, g_Wvt);
    cudaGetSymbolAddress((void**)&pcv, g_cv);
    cudaGetSymbolAddress((void**)&pxth, g_xth);
    cudaGetSymbolAddress((void**)&pxtl, g_xtl);
    cudaGetSymbolAddress((void**)&pMh, g_Mh);
    cudaGetSymbolAddress((void**)&pMl, g_Ml);

    const long CN = (long)CC * NPIX;
    const long C2 = (long)CC * CC;

    splitx_kernel<<<dim3(128, 8, 16), 256>>>(x);
    rowsum_kernel<<<512, 256>>>(x);
    wvt_kernel<<<256, 256>>>(wv);
    proj_sums<<<16, 256>>>(wq, wk);
    // G partials: x x^T, split-K 2 (z = kc*16 + b), per-CTA K = 2048
    mgemm<<<dim3(2, 2, 32), 256>>>(x, x, pGp, 2048, NPIX, NPIX, CN, CN, C2, 15, 4, 2048);
    reduceg_kernel<<<1024, 256>>>();
    // T = Wq G ; L = T Wk^T ; softmax ; M = A Wv^T
    mgemm<<<dim3(2, 2, 16), 256>>>(wq, pG, pT, CC, CC, CC, 0, C2, C2, 255, 8, 0);
    mgemm<<<dim3(2, 2, 16), 256>>>(pT, wk, pL, CC, CC, CC, C2, 0, C2, 255, 8, 0);
    softmax_kernel<<<4096, 256>>>(bq, bk);
    mgemm<<<dim3(2, 2, 16), 256>>>(pL, pWvt, pM, CC, CC, CC, C2, 0, C2, 255, 8, 0);
    cvec_kernel<<<16, 256>>>(bv);
    splitm_kernel<<<1024, 256>>>();
    // out = x + M x + cv  (A = M hi/lo [c][d], B = x^T hi/lo [n][d])
    cgemm<<<dim3(32, 2, 16), 256>>>(pMh, pMl, pxth, pxtl, x, pcv, out);
}

// round 8
// speedup vs baseline: 1.8969x; 1.2057x over previous
#include <cuda_runtime.h>
#include <cuda_bf16.h>

#define BB 16
#define CC 256
#define NPIX 4096
typedef __nv_bfloat16 bf16;
typedef unsigned int u32;
typedef unsigned short u16;

// ---------------- scratch (device globals) ----------------
__device__ float g_G[BB * CC * CC];
__device__ float g_Gp[2 * BB * CC * CC];
__device__ float g_T[BB * CC * CC];
__device__ float g_L[BB * CC * CC];
__device__ float g_M[BB * CC * CC];
__device__ float g_Wvt[CC * CC];
__device__ float g_sx[BB * CC], g_qs[BB * CC], g_ks[BB * CC], g_cv[BB * CC];
__device__ __align__(16) bf16 g_xth[(size_t)BB * NPIX * CC];
__device__ __align__(16) bf16 g_xtl[(size_t)BB * NPIX * CC];
__device__ __align__(16) bf16 g_Mh[BB * CC * CC];
__device__ __align__(16) bf16 g_Ml[BB * CC * CC];

// ---------------- helpers ----------------
__device__ __forceinline__ void split2(float f, bf16& h, bf16& l) {
    h = __float2bfloat16(f);
    l = __float2bfloat16(f - __bfloat162float(h));
}
__device__ __forceinline__ u32 pack2(bf16 a, bf16 b) {
    return (u32)__bfloat16_as_ushort(a) | ((u32)__bfloat16_as_ushort(b) << 16);
}
__device__ __forceinline__ void cvt4(float4 v, uint2& h, uint2& l) {
    bf16 h0, l0, h1, l1, h2, l2, h3, l3;
    split2(v.x, h0, l0); split2(v.y, h1, l1);
    split2(v.z, h2, l2); split2(v.w, h3, l3);
    h = make_uint2(pack2(h0, h1), pack2(h2, h3));
    l = make_uint2(pack2(l0, l1), pack2(l2, l3));
}
__device__ __forceinline__ void mma16816(float* c, const u32* a, const u32* b) {
    asm volatile(
        "mma.sync.aligned.m16n8k16.row.col.f32.bf16.bf16.f32 "
        "{%0,%1,%2,%3}, {%4,%5,%6,%7}, {%8,%9}, {%0,%1,%2,%3};"
        : "+f"(c[0]), "+f"(c[1]), "+f"(c[2]), "+f"(c[3])
        : "r"(a[0]), "r"(a[1]), "r"(a[2]), "r"(a[3]), "r"(b[0]), "r"(b[1]));
}

// ---------------- fp32-input hi/lo mma GEMM (proven core + split-K) --------
__global__ void __launch_bounds__(256, 1) mgemm(
    const float* __restrict__ A, const float* __restrict__ B, float* __restrict__ C,
    int K, int lda, int ldb, long sA, long sB, long sC,
    int bmask, int sb, int kps)
{
    __shared__ __align__(16) u16 Ah[128][40], Al[128][40];
    __shared__ __align__(16) u16 Bh[128][40], Bl[128][40];
    int tid = threadIdx.x, lane = tid & 31, wid = tid >> 5;
    int wm = wid >> 2, wn = wid & 3;
    int bx = blockIdx.x, by = blockIdx.y, z = blockIdx.z;
    int b = z & bmask;
    int kbase = (z >> sb) * kps;
    const float* Ab = A + (size_t)b * sA + (size_t)(by * 128) * lda + kbase;
    const float* Bb = B + (size_t)b * sB + kbase;
    float acc[4][4][4] = {};
    float4 va[4], vb[4];
    int arow = tid >> 1, acb = (tid & 1) * 16;
    auto LDG = [&](int k0) {
#pragma unroll
        for (int j = 0; j < 4; j++) {
            va[j] = *(const float4*)(Ab + (size_t)arow * lda + k0 + acb + 4 * j);
            vb[j] = *(const float4*)(Bb + (size_t)(bx * 128 + arow) * ldb + k0 + acb + 4 * j);
        }
    };
    auto STS = [&]() {
#pragma unroll
        for (int j = 0; j < 4; j++) {
            uint2 h, l;
            cvt4(va[j], h, l);
            *(uint2*)&Ah[arow][acb + 4 * j] = h;
            *(uint2*)&Al[arow][acb + 4 * j] = l;
            cvt4(vb[j], h, l);
            *(uint2*)&Bh[arow][acb + 4 * j] = h;
            *(uint2*)&Bl[arow][acb + 4 * j] = l;
        }
    };
    int T = K >> 5;
    LDG(0);
    for (int t = 0; t < T; t++) {
        STS();
        __syncthreads();
        if (t + 1 < T) LDG((t + 1) << 5);
#pragma unroll
        for (int kc = 0; kc < 32; kc += 16) {
            int kk = kc + (lane & 3) * 2;
            u32 afh[4][4], afl[4][4], bfh[4][2], bfl[4][2];
#pragma unroll
            for (int mf = 0; mf < 4; mf++) {
                int r0 = wm * 64 + mf * 16 + (lane >> 2);
                afh[mf][0] = *(const u32*)&Ah[r0][kk];
                afh[mf][1] = *(const u32*)&Ah[r0 + 8][kk];
                afh[mf][2] = *(const u32*)&Ah[r0][kk + 8];
                afh[mf][3] = *(const u32*)&Ah[r0 + 8][kk + 8];
                afl[mf][0] = *(const u32*)&Al[r0][kk];
                afl[mf][1] = *(const u32*)&Al[r0 + 8][kk];
                afl[mf][2] = *(const u32*)&Al[r0][kk + 8];
                afl[mf][3] = *(const u32*)&Al[r0 + 8][kk + 8];
            }
#pragma unroll
            for (int nf = 0; nf < 4; nf++) {
                int c0 = wn * 32 + nf * 8 + (lane >> 2);
                bfh[nf][0] = *(const u32*)&Bh[c0][kk];
                bfh[nf][1] = *(const u32*)&Bh[c0][kk + 8];
                bfl[nf][0] = *(const u32*)&Bl[c0][kk];
                bfl[nf][1] = *(const u32*)&Bl[c0][kk + 8];
            }
#pragma unroll
            for (int mf = 0; mf < 4; mf++)
#pragma unroll
                for (int nf = 0; nf < 4; nf++) {
                    mma16816(acc[mf][nf], afh[mf], bfh[nf]);
                    mma16816(acc[mf][nf], afh[mf], bfl[nf]);
                    mma16816(acc[mf][nf], afl[mf], bfh[nf]);
                }
        }
        __syncthreads();
    }
#pragma unroll
    for (int mf = 0; mf < 4; mf++) {
        int rg = by * 128 + wm * 64 + mf * 16 + (lane >> 2);
#pragma unroll
        for (int nf = 0; nf < 4; nf++) {
            int cg = bx * 128 + wn * 32 + nf * 8 + (lane & 3) * 2;
            float* a = acc[mf][nf];
            float* p = C + (size_t)z * sC + (size_t)rg * CC + cg;
            *(float2*)p = make_float2(a[0], a[1]);
            *(float2*)(p + 8 * CC) = make_float2(a[2], a[3]);
        }
    }
}

// ---------------- bf16-input stage C GEMM: out = x + M x + cv ---------------
__global__ void __launch_bounds__(256, 1) cgemm(
    const bf16* __restrict__ Ahg, const bf16* __restrict__ Alg,
    const bf16* __restrict__ Bhg, const bf16* __restrict__ Blg,
    const float* __restrict__ xres, const float* __restrict__ cvv,
    float* __restrict__ outp)
{
    __shared__ __align__(16) u16 Ah[128][40], Al[128][40];
    __shared__ __align__(16) u16 Bh[128][40], Bl[128][40];
    int tid = threadIdx.x, lane = tid & 31, wid = tid >> 5;
    int wm = wid >> 2, wn = wid & 3;
    int bx = blockIdx.x, by = blockIdx.y, b = blockIdx.z;
    const bf16* Abh = Ahg + (size_t)b * CC * CC + (size_t)(by * 128) * CC;
    const bf16* Abl = Alg + (size_t)b * CC * CC + (size_t)(by * 128) * CC;
    const bf16* Bbh = Bhg + (size_t)b * NPIX * CC + (size_t)(bx * 128) * CC;
    const bf16* Bbl = Blg + (size_t)b * NPIX * CC + (size_t)(bx * 128) * CC;
    float acc[4][4][4] = {};
    uint4 rah[2], ral[2], rbh[2], rbl[2];
    int arow = tid >> 1, acb = (tid & 1) * 16;
    auto LDG = [&](int k0) {
#pragma unroll
        for (int j = 0; j < 2; j++) {
            rah[j] = *(const uint4*)(Abh + (size_t)arow * CC + k0 + acb + 8 * j);
            ral[j] = *(const uint4*)(Abl + (size_t)arow * CC + k0 + acb + 8 * j);
            rbh[j] = *(const uint4*)(Bbh + (size_t)arow * CC + k0 + acb + 8 * j);
            rbl[j] = *(const uint4*)(Bbl + (size_t)arow * CC + k0 + acb + 8 * j);
        }
    };
    LDG(0);
    for (int t = 0; t < 8; t++) {
#pragma unroll
        for (int j = 0; j < 2; j++) {
            *(uint4*)&Ah[arow][acb + 8 * j] = rah[j];
            *(uint4*)&Al[arow][acb + 8 * j] = ral[j];
            *(uint4*)&Bh[arow][acb + 8 * j] = rbh[j];
            *(uint4*)&Bl[arow][acb + 8 * j] = rbl[j];
        }
        __syncthreads();
        if (t + 1 < 8) LDG((t + 1) << 5);
#pragma unroll
        for (int kc = 0; kc < 32; kc += 16) {
            int kk = kc + (lane & 3) * 2;
            u32 afh[4][4], afl[4][4], bfh[4][2], bfl[4][2];
#pragma unroll
            for (int mf = 0; mf < 4; mf++) {
                int r0 = wm * 64 + mf * 16 + (lane >> 2);
                afh[mf][0] = *(const u32*)&Ah[r0][kk];
                afh[mf][1] = *(const u32*)&Ah[r0 + 8][kk];
                afh[mf][2] = *(const u32*)&Ah[r0][kk + 8];
                afh[mf][3] = *(const u32*)&Ah[r0 + 8][kk + 8];
                afl[mf][0] = *(const u32*)&Al[r0][kk];
                afl[mf][1] = *(const u32*)&Al[r0 + 8][kk];
                afl[mf][2] = *(const u32*)&Al[r0][kk + 8];
                afl[mf][3] = *(const u32*)&Al[r0 + 8][kk + 8];
            }
#pragma unroll
            for (int nf = 0; nf < 4; nf++) {
                int c0 = wn * 32 + nf * 8 + (lane >> 2);
                bfh[nf][0] = *(const u32*)&Bh[c0][kk];
                bfh[nf][1] = *(const u32*)&Bh[c0][kk + 8];
                bfl[nf][0] = *(const u32*)&Bl[c0][kk];
                bfl[nf][1] = *(const u32*)&Bl[c0][kk + 8];
            }
#pragma unroll
            for (int mf = 0; mf < 4; mf++)
#pragma unroll
                for (int nf = 0; nf < 4; nf++) {
                    mma16816(acc[mf][nf], afh[mf], bfh[nf]);
                    mma16816(acc[mf][nf], afh[mf], bfl[nf]);
                    mma16816(acc[mf][nf], afl[mf], bfh[nf]);
                }
        }
        __syncthreads();
    }
#pragma unroll
    for (int mf = 0; mf < 4; mf++) {
        int rg = by * 128 + wm * 64 + mf * 16 + (lane >> 2);
#pragma unroll
        for (int nf = 0; nf < 4; nf++) {
            int cg = bx * 128 + wn * 32 + nf * 8 + (lane & 3) * 2;
            float* a = acc[mf][nf];
            size_t o0 = (size_t)b * CC * NPIX + (size_t)rg * NPIX + cg;
            size_t o1 = o0 + 8 * NPIX;
            float cv0 = cvv[b * CC + rg];
            float cv1 = cvv[b * CC + rg + 8];
            float2 x0 = *(const float2*)(xres + o0);
            float2 x1 = *(const float2*)(xres + o1);
            *(float2*)(outp + o0) = make_float2(x0.x + a[0] + cv0, x0.y + a[1] + cv0);
            *(float2*)(outp + o1) = make_float2(x1.x + a[2] + cv1, x1.y + a[3] + cv1);
        }
    }
}

// ---------------- split + transpose x -> xth/xtl ----------------
__global__ void splitx_kernel(const float* __restrict__ x) {
    __shared__ u32 st[32][33];
    int b = blockIdx.z, c0 = blockIdx.y * 32, n0 = blockIdx.x * 32;
    int tid = threadIdx.x;
    int c = tid >> 3, n4 = (tid & 7) * 4;
    float4 v = *(const float4*)(x + ((size_t)(b * CC + c0 + c)) * NPIX + n0 + n4);
    bf16 h[4], l[4];
    split2(v.x, h[0], l[0]); split2(v.y, h[1], l[1]);
    split2(v.z, h[2], l[2]); split2(v.w, h[3], l[3]);
#pragma unroll
    for (int j = 0; j < 4; j++)
        st[c][n4 + j] = (u32)__bfloat16_as_ushort(h[j]) | ((u32)__bfloat16_as_ushort(l[j]) << 16);
    __syncthreads();
    int n = tid >> 3, c4 = (tid & 7) * 4;
    bf16 th[4], tl[4];
#pragma unroll
    for (int j = 0; j < 4; j++) {
        u32 w = st[c4 + j][n];
        th[j] = __ushort_as_bfloat16((u16)(w & 0xFFFF));
        tl[j] = __ushort_as_bfloat16((u16)(w >> 16));
    }
    size_t to = ((size_t)b * NPIX + n0 + n) * CC + c0 + c4;
    *(uint2*)(g_xth + to) = make_uint2(pack2(th[0], th[1]), pack2(th[2], th[3]));
    *(uint2*)(g_xtl + to) = make_uint2(pack2(tl[0], tl[1]), pack2(tl[2], tl[3]));
}

// ---------------- row sums ----------------
__global__ void rowsum_kernel(const float* __restrict__ x) {
    int row = blockIdx.x * 8 + (threadIdx.x >> 5);
    int lane = threadIdx.x & 31;
    const float* p = x + (size_t)row * NPIX;
    float s = 0.f;
    for (int i = lane; i < NPIX; i += 32) s += p[i];
#pragma unroll
    for (int o = 16; o; o >>= 1) s += __shfl_xor_sync(0xFFFFFFFFu, s, o);
    if (lane == 0) g_sx[row] = s;
}

// ---------------- qs/ks: warp per output, coalesced -------------------------
__global__ void proj_sums(const float* __restrict__ wq, const float* __restrict__ wk) {
    __shared__ float sxs[CC];
    int b = blockIdx.x, mat = blockIdx.y;
    int tid = threadIdx.x, lane = tid & 31, wid = tid >> 5;
    sxs[tid] = g_sx[b * CC + tid];
    __syncthreads();
    const float* w = mat ? wk : wq;
    float* outv = mat ? g_ks : g_qs;
#pragma unroll 4
    for (int i = 0; i < 32; i++) {
        int o = wid * 32 + i;
        const float* r = w + o * CC;
        float s = 0.f;
#pragma unroll
        for (int j = 0; j < 8; j++) {
            int cidx = lane + 32 * j;
            s += r[cidx] * sxs[cidx];
        }
#pragma unroll
        for (int off = 16; off; off >>= 1) s += __shfl_down_sync(0xFFFFFFFFu, s, off);
        if (lane == 0) outv[b * CC + o] = s;
    }
}

// ---------------- softmax (+ folded cv = A bv) ------------------------------
__global__ void softmax_kernel(const float* __restrict__ bq, const float* __restrict__ bk,
                               const float* __restrict__ bv) {
    int row = blockIdx.x;
    int b = row >> 8, c = row & 255;
    int d = threadIdx.x;
    __shared__ float red[256];
    float v = g_L[(size_t)row * CC + d];
    float bqc = bq[c];
    v += g_qs[b * CC + c] * bk[d] + bqc * g_ks[b * CC + d] + 4096.f * bqc * bk[d];
    v *= 0.0625f;
    red[d] = v;
    __syncthreads();
#pragma unroll
    for (int s = 128; s; s >>= 1) { if (d < s) red[d] = fmaxf(red[d], red[d + s]); __syncthreads(); }
    float m = red[0];
    __syncthreads();
    float e = __expf(v - m);
    red[d] = e;
    __syncthreads();
#pragma unroll
    for (int s = 128; s; s >>= 1) { if (d < s) red[d] += red[d + s]; __syncthreads(); }
    float p = e * (1.0f / red[0]);
    g_L[(size_t)row * CC + d] = p;
    __syncthreads();
    red[d] = p * bv[d];
    __syncthreads();
#pragma unroll
    for (int s = 128; s; s >>= 1) { if (d < s) red[d] += red[d + s]; __syncthreads(); }
    if (d == 0) g_cv[row] = red[0];
}

// ---------------- misc small kernels ----------------------------------------
__global__ void wvt_kernel(const float* __restrict__ wv) {
    int d = blockIdx.x, e = threadIdx.x;
    g_Wvt[e * CC + d] = wv[d * CC + e];
}
__global__ void splitm_kernel() {
    int i = (blockIdx.x * 256 + threadIdx.x) * 4;
    float4 v = *(const float4*)(g_M + i);
    bf16 h[4], l[4];
    split2(v.x, h[0], l[0]); split2(v.y, h[1], l[1]);
    split2(v.z, h[2], l[2]); split2(v.w, h[3], l[3]);
    *(uint2*)(g_Mh + i) = make_uint2(pack2(h[0], h[1]), pack2(h[2], h[3]));
    *(uint2*)(g_Ml + i) = make_uint2(pack2(l[0], l[1]), pack2(l[2], l[3]));
}
__global__ void reduceg_kernel() {
    int i = (blockIdx.x * 256 + threadIdx.x) * 4;
    float4 a = *(const float4*)(g_Gp + i);
    float4 b = *(const float4*)(g_Gp + BB * CC * CC + i);
    *(float4*)(g_G + i) = make_float4(a.x + b.x, a.y + b.y, a.z + b.z, a.w + b.w);
}

// ---------------- launcher ----------------
extern "C" void kernel_launch(void* const* d_in, const int* in_sizes, int n_in,
                              void* d_out, int out_size) {
    const float* x  = (const float*)d_in[0];
    const float* wq = (const float*)d_in[1];
    const float* bq = (const float*)d_in[2];
    const float* wk = (const float*)d_in[3];
    const float* bk = (const float*)d_in[4];
    const float* wv = (const float*)d_in[5];
    const float* bv = (const float*)d_in[6];
    float* out = (float*)d_out;

    float *pG, *pGp, *pT, *pL, *pM, *pWvt, *pcv;
    bf16 *pxth, *pxtl, *pMh, *pMl;
    cudaGetSymbolAddress((void**)&pG, g_G);
    cudaGetSymbolAddress((void**)&pGp, g_Gp);
    cudaGetSymbolAddress((void**)&pT, g_T);
    cudaGetSymbolAddress((void**)&pL, g_L);
    cudaGetSymbolAddress((void**)&pM, g_M);
    cudaGetSymbolAddress((void**)&pWvt, g_Wvt);
    cudaGetSymbolAddress((void**)&pcv, g_cv);
    cudaGetSymbolAddress((void**)&pxth, g_xth);
    cudaGetSymbolAddress((void**)&pxtl, g_xtl);
    cudaGetSymbolAddress((void**)&pMh, g_Mh);
    cudaGetSymbolAddress((void**)&pMl, g_Ml);

    const long CN = (long)CC * NPIX;
    const long C2 = (long)CC * CC;

    splitx_kernel<<<dim3(128, 8, 16), 256>>>(x);
    rowsum_kernel<<<512, 256>>>(x);
    wvt_kernel<<<256, 256>>>(wv);
    proj_sums<<<dim3(16, 2), 256>>>(wq, wk);
    // G partials: x x^T, split-K 2 (z = kc*16 + b), per-CTA K = 2048
    mgemm<<<dim3(2, 2, 32), 256>>>(x, x, pGp, 2048, NPIX, NPIX, CN, CN, C2, 15, 4, 2048);
    reduceg_kernel<<<1024, 256>>>();
    // T = Wq G ; L = T Wk^T ; softmax(+cv) ; M = A Wv^T
    mgemm<<<dim3(2, 2, 16), 256>>>(wq, pG, pT, CC, CC, CC, 0, C2, C2, 255, 8, 0);
    mgemm<<<dim3(2, 2, 16), 256>>>(pT, wk, pL, CC, CC, CC, C2, 0, C2, 255, 8, 0);
    softmax_kernel<<<4096, 256>>>(bq, bk, bv);
    mgemm<<<dim3(2, 2, 16), 256>>>(pL, pWvt, pM, CC, CC, CC, C2, 0, C2, 255, 8, 0);
    splitm_kernel<<<1024, 256>>>();
    // out = x + M x + cv  (A = M hi/lo [c][d], B = x^T hi/lo [n][d])
    cgemm<<<dim3(32, 2, 16), 256>>>(pMh, pMl, pxth, pxtl, x, pcv, out);
}

// round 9
// speedup vs baseline: 2.0626x; 1.0874x over previous
#include <cuda_runtime.h>
#include <cuda_bf16.h>

#define BB 16
#define CC 256
#define NPIX 4096
typedef __nv_bfloat16 bf16;
typedef unsigned int u32;
typedef unsigned short u16;

// ---------------- scratch (device globals) ----------------
__device__ float g_G[BB * CC * CC];
__device__ float g_Gp[2 * BB * CC * CC];
__device__ float g_T[BB * CC * CC];
__device__ float g_L[BB * CC * CC];
__device__ float g_M[BB * CC * CC];
__device__ float g_Wvt[CC * CC];
__device__ float g_sx[BB * CC], g_qs[BB * CC], g_ks[BB * CC], g_cv[BB * CC];
__device__ __align__(16) bf16 g_yh[(size_t)BB * CC * NPIX];
__device__ __align__(16) bf16 g_yl[(size_t)BB * CC * NPIX];
__device__ __align__(16) bf16 g_xth[(size_t)BB * NPIX * CC];
__device__ __align__(16) bf16 g_xtl[(size_t)BB * NPIX * CC];
__device__ __align__(16) bf16 g_Mh[BB * CC * CC];
__device__ __align__(16) bf16 g_Ml[BB * CC * CC];

// ---------------- helpers ----------------
__device__ __forceinline__ void split2(float f, bf16& h, bf16& l) {
    h = __float2bfloat16(f);
    l = __float2bfloat16(f - __bfloat162float(h));
}
__device__ __forceinline__ u32 pack2(bf16 a, bf16 b) {
    return (u32)__bfloat16_as_ushort(a) | ((u32)__bfloat16_as_ushort(b) << 16);
}
__device__ __forceinline__ void cvt4(float4 v, uint2& h, uint2& l) {
    bf16 h0, l0, h1, l1, h2, l2, h3, l3;
    split2(v.x, h0, l0); split2(v.y, h1, l1);
    split2(v.z, h2, l2); split2(v.w, h3, l3);
    h = make_uint2(pack2(h0, h1), pack2(h2, h3));
    l = make_uint2(pack2(l0, l1), pack2(l2, l3));
}
__device__ __forceinline__ void mma16816(float* c, const u32* a, const u32* b) {
    asm volatile(
        "mma.sync.aligned.m16n8k16.row.col.f32.bf16.bf16.f32 "
        "{%0,%1,%2,%3}, {%4,%5,%6,%7}, {%8,%9}, {%0,%1,%2,%3};"
        : "+f"(c[0]), "+f"(c[1]), "+f"(c[2]), "+f"(c[3])
        : "r"(a[0]), "r"(a[1]), "r"(a[2]), "r"(a[3]), "r"(b[0]), "r"(b[1]));
}
__device__ __forceinline__ void cp16(u32 saddr, const void* g) {
    asm volatile("cp.async.ca.shared.global [%0], [%1], 16;" :: "r"(saddr), "l"(g));
}

// ---------------- 2-stage cp.async bf16 hi/lo GEMM --------------------------
// A: bf16 hi/lo rows = M (ld lda). B: bf16 hi/lo rows = N (ld ldb). K-major.
// EPI 0: fp32 C at z*sC (ldc=CC). EPI 1: out = x + D + cv.
#define STG_US 20480  // u16 per stage: 4 tiles * 128*40
template <int EPI>
__global__ void __launch_bounds__(256, 1) bgemm(
    const bf16* __restrict__ Ahg, const bf16* __restrict__ Alg,
    const bf16* __restrict__ Bhg, const bf16* __restrict__ Blg,
    float* __restrict__ C, int T, int lda, int ldb, long sA, long sB, long sC,
    int bmask, int sb, int kps,
    const float* __restrict__ xres, const float* __restrict__ cvv, float* __restrict__ outp)
{
    extern __shared__ __align__(16) u16 smp[];
    int tid = threadIdx.x, lane = tid & 31, wid = tid >> 5;
    int wm = wid >> 2, wn = wid & 3;
    int bx = blockIdx.x, by = blockIdx.y, z = blockIdx.z;
    int b = z & bmask;
    int kbase = (z >> sb) * kps;

    const bf16* Abh = Ahg + (size_t)b * sA + (size_t)(by * 128) * lda + kbase;
    const bf16* Abl = Alg + (size_t)b * sA + (size_t)(by * 128) * lda + kbase;
    const bf16* Bbh = Bhg + (size_t)b * sB + (size_t)(bx * 128) * ldb + kbase;
    const bf16* Bbl = Blg + (size_t)b * sB + (size_t)(bx * 128) * ldb + kbase;

    u32 sbase;
    asm("{ .reg .u64 t; cvta.to.shared.u64 t, %1; cvt.u32.u64 %0, t; }"
        : "=r"(sbase) : "l"(smp));

    auto PREF = [&](int t) {
        if (t < T) {
            int k0 = t * 32, st = t & 1;
            u32 s0 = sbase + (u32)(st * STG_US) * 2;
#pragma unroll
            for (int j = 0; j < 2; j++) {
                int idx = tid * 2 + j;          // 0..511
                int r = idx >> 2, c8 = (idx & 3) * 8;
                u32 off = (u32)(r * 40 + c8) * 2;
                cp16(s0 + off,         Abh + (size_t)r * lda + k0 + c8);
                cp16(s0 + off + 10240, Abl + (size_t)r * lda + k0 + c8);
                cp16(s0 + off + 20480, Bbh + (size_t)r * ldb + k0 + c8);
                cp16(s0 + off + 30720, Bbl + (size_t)r * ldb + k0 + c8);
            }
        }
        asm volatile("cp.async.commit_group;" ::: "memory");
    };

    float acc[4][4][4] = {};
    PREF(0);
    for (int t = 0; t < T; t++) {
        PREF(t + 1);
        asm volatile("cp.async.wait_group 1;" ::: "memory");
        __syncthreads();
        int st = t & 1;
        u16 (*Ah)[40] = (u16(*)[40])(smp + st * STG_US);
        u16 (*Al)[40] = (u16(*)[40])(smp + st * STG_US + 5120);
        u16 (*Bh)[40] = (u16(*)[40])(smp + st * STG_US + 10240);
        u16 (*Bl)[40] = (u16(*)[40])(smp + st * STG_US + 15360);
#pragma unroll
        for (int kc = 0; kc < 32; kc += 16) {
            int kk = kc + (lane & 3) * 2;
            u32 afh[4][4], afl[4][4], bfh[4][2], bfl[4][2];
#pragma unroll
            for (int mf = 0; mf < 4; mf++) {
                int r0 = wm * 64 + mf * 16 + (lane >> 2);
                afh[mf][0] = *(const u32*)&Ah[r0][kk];
                afh[mf][1] = *(const u32*)&Ah[r0 + 8][kk];
                afh[mf][2] = *(const u32*)&Ah[r0][kk + 8];
                afh[mf][3] = *(const u32*)&Ah[r0 + 8][kk + 8];
                afl[mf][0] = *(const u32*)&Al[r0][kk];
                afl[mf][1] = *(const u32*)&Al[r0 + 8][kk];
                afl[mf][2] = *(const u32*)&Al[r0][kk + 8];
                afl[mf][3] = *(const u32*)&Al[r0 + 8][kk + 8];
            }
#pragma unroll
            for (int nf = 0; nf < 4; nf++) {
                int c0 = wn * 32 + nf * 8 + (lane >> 2);
                bfh[nf][0] = *(const u32*)&Bh[c0][kk];
                bfh[nf][1] = *(const u32*)&Bh[c0][kk + 8];
                bfl[nf][0] = *(const u32*)&Bl[c0][kk];
                bfl[nf][1] = *(const u32*)&Bl[c0][kk + 8];
            }
#pragma unroll
            for (int mf = 0; mf < 4; mf++)
#pragma unroll
                for (int nf = 0; nf < 4; nf++) {
                    mma16816(acc[mf][nf], afh[mf], bfh[nf]);
                    mma16816(acc[mf][nf], afh[mf], bfl[nf]);
                    mma16816(acc[mf][nf], afl[mf], bfh[nf]);
                }
        }
        __syncthreads();
    }

#pragma unroll
    for (int mf = 0; mf < 4; mf++) {
        int rg = by * 128 + wm * 64 + mf * 16 + (lane >> 2);
#pragma unroll
        for (int nf = 0; nf < 4; nf++) {
            int cg = bx * 128 + wn * 32 + nf * 8 + (lane & 3) * 2;
            float* a = acc[mf][nf];
            if (EPI == 0) {
                float* p = C + (size_t)z * sC + (size_t)rg * CC + cg;
                *(float2*)p = make_float2(a[0], a[1]);
                *(float2*)(p + 8 * CC) = make_float2(a[2], a[3]);
            } else {
                size_t o0 = (size_t)b * CC * NPIX + (size_t)rg * NPIX + cg;
                size_t o1 = o0 + 8 * NPIX;
                float cv0 = cvv[b * CC + rg];
                float cv1 = cvv[b * CC + rg + 8];
                float2 x0 = *(const float2*)(xres + o0);
                float2 x1 = *(const float2*)(xres + o1);
                *(float2*)(outp + o0) = make_float2(x0.x + a[0] + cv0, x0.y + a[1] + cv0);
                *(float2*)(outp + o1) = make_float2(x1.x + a[2] + cv1, x1.y + a[3] + cv1);
            }
        }
    }
}

// ---------------- fp32-input hi/lo mma GEMM (small GEMMs; proven) -----------
__global__ void __launch_bounds__(256, 1) mgemm(
    const float* __restrict__ A, const float* __restrict__ B, float* __restrict__ C,
    int K, int lda, int ldb, long sA, long sB, long sC)
{
    __shared__ __align__(16) u16 Ah[128][40], Al[128][40];
    __shared__ __align__(16) u16 Bh[128][40], Bl[128][40];
    int tid = threadIdx.x, lane = tid & 31, wid = tid >> 5;
    int wm = wid >> 2, wn = wid & 3;
    int bx = blockIdx.x, by = blockIdx.y, b = blockIdx.z;
    const float* Ab = A + (size_t)b * sA + (size_t)(by * 128) * lda;
    const float* Bb = B + (size_t)b * sB;
    float acc[4][4][4] = {};
    float4 va[4], vb[4];
    int arow = tid >> 1, acb = (tid & 1) * 16;
    auto LDG = [&](int k0) {
#pragma unroll
        for (int j = 0; j < 4; j++) {
            va[j] = *(const float4*)(Ab + (size_t)arow * lda + k0 + acb + 4 * j);
            vb[j] = *(const float4*)(Bb + (size_t)(bx * 128 + arow) * ldb + k0 + acb + 4 * j);
        }
    };
    auto STS = [&]() {
#pragma unroll
        for (int j = 0; j < 4; j++) {
            uint2 h, l;
            cvt4(va[j], h, l);
            *(uint2*)&Ah[arow][acb + 4 * j] = h;
            *(uint2*)&Al[arow][acb + 4 * j] = l;
            cvt4(vb[j], h, l);
            *(uint2*)&Bh[arow][acb + 4 * j] = h;
            *(uint2*)&Bl[arow][acb + 4 * j] = l;
        }
    };
    int T = K >> 5;
    LDG(0);
    for (int t = 0; t < T; t++) {
        STS();
        __syncthreads();
        if (t + 1 < T) LDG((t + 1) << 5);
#pragma unroll
        for (int kc = 0; kc < 32; kc += 16) {
            int kk = kc + (lane & 3) * 2;
            u32 afh[4][4], afl[4][4], bfh[4][2], bfl[4][2];
#pragma unroll
            for (int mf = 0; mf < 4; mf++) {
                int r0 = wm * 64 + mf * 16 + (lane >> 2);
                afh[mf][0] = *(const u32*)&Ah[r0][kk];
                afh[mf][1] = *(const u32*)&Ah[r0 + 8][kk];
                afh[mf][2] = *(const u32*)&Ah[r0][kk + 8];
                afh[mf][3] = *(const u32*)&Ah[r0 + 8][kk + 8];
                afl[mf][0] = *(const u32*)&Al[r0][kk];
                afl[mf][1] = *(const u32*)&Al[r0 + 8][kk];
                afl[mf][2] = *(const u32*)&Al[r0][kk + 8];
                afl[mf][3] = *(const u32*)&Al[r0 + 8][kk + 8];
            }
#pragma unroll
            for (int nf = 0; nf < 4; nf++) {
                int c0 = wn * 32 + nf * 8 + (lane >> 2);
                bfh[nf][0] = *(const u32*)&Bh[c0][kk];
                bfh[nf][1] = *(const u32*)&Bh[c0][kk + 8];
                bfl[nf][0] = *(const u32*)&Bl[c0][kk];
                bfl[nf][1] = *(const u32*)&Bl[c0][kk + 8];
            }
#pragma unroll
            for (int mf = 0; mf < 4; mf++)
#pragma unroll
                for (int nf = 0; nf < 4; nf++) {
                    mma16816(acc[mf][nf], afh[mf], bfh[nf]);
                    mma16816(acc[mf][nf], afh[mf], bfl[nf]);
                    mma16816(acc[mf][nf], afl[mf], bfh[nf]);
                }
        }
        __syncthreads();
    }
#pragma unroll
    for (int mf = 0; mf < 4; mf++) {
        int rg = by * 128 + wm * 64 + mf * 16 + (lane >> 2);
#pragma unroll
        for (int nf = 0; nf < 4; nf++) {
            int cg = bx * 128 + wn * 32 + nf * 8 + (lane & 3) * 2;
            float* a = acc[mf][nf];
            float* p = C + (size_t)b * sC + (size_t)rg * CC + cg;
            *(float2*)p = make_float2(a[0], a[1]);
            *(float2*)(p + 8 * CC) = make_float2(a[2], a[3]);
        }
    }
}

// ---------------- split x -> yh/yl and transposed xth/xtl -------------------
__global__ void splitx_kernel(const float* __restrict__ x) {
    __shared__ u32 st[32][33];
    int b = blockIdx.z, c0 = blockIdx.y * 32, n0 = blockIdx.x * 32;
    int tid = threadIdx.x;
    int c = tid >> 3, n4 = (tid & 7) * 4;
    float4 v = *(const float4*)(x + ((size_t)(b * CC + c0 + c)) * NPIX + n0 + n4);
    bf16 h[4], l[4];
    split2(v.x, h[0], l[0]); split2(v.y, h[1], l[1]);
    split2(v.z, h[2], l[2]); split2(v.w, h[3], l[3]);
    size_t yo = ((size_t)(b * CC + c0 + c)) * NPIX + n0 + n4;
    *(uint2*)(g_yh + yo) = make_uint2(pack2(h[0], h[1]), pack2(h[2], h[3]));
    *(uint2*)(g_yl + yo) = make_uint2(pack2(l[0], l[1]), pack2(l[2], l[3]));
#pragma unroll
    for (int j = 0; j < 4; j++)
        st[c][n4 + j] = (u32)__bfloat16_as_ushort(h[j]) | ((u32)__bfloat16_as_ushort(l[j]) << 16);
    __syncthreads();
    int n = tid >> 3, c4 = (tid & 7) * 4;
    bf16 th[4], tl[4];
#pragma unroll
    for (int j = 0; j < 4; j++) {
        u32 w = st[c4 + j][n];
        th[j] = __ushort_as_bfloat16((u16)(w & 0xFFFF));
        tl[j] = __ushort_as_bfloat16((u16)(w >> 16));
    }
    size_t to = ((size_t)b * NPIX + n0 + n) * CC + c0 + c4;
    *(uint2*)(g_xth + to) = make_uint2(pack2(th[0], th[1]), pack2(th[2], th[3]));
    *(uint2*)(g_xtl + to) = make_uint2(pack2(tl[0], tl[1]), pack2(tl[2], tl[3]));
}

// ---------------- row sums (vectorized, high MLP) ---------------------------
__global__ void rowsum_kernel(const float* __restrict__ x) {
    int row = blockIdx.x * 8 + (threadIdx.x >> 5);
    int lane = threadIdx.x & 31;
    const float4* p = (const float4*)(x + (size_t)row * NPIX);
    float s = 0.f;
#pragma unroll
    for (int i = 0; i < 32; i++) {
        float4 v = p[lane + 32 * i];
        s += (v.x + v.y) + (v.z + v.w);
    }
#pragma unroll
    for (int o = 16; o; o >>= 1) s += __shfl_xor_sync(0xFFFFFFFFu, s, o);
    if (lane == 0) g_sx[row] = s;
}

// ---------------- qs/ks: warp per output, grid-parallel ---------------------
__global__ void proj_sums(const float* __restrict__ wq, const float* __restrict__ wk) {
    __shared__ float sxs[CC];
    int b = blockIdx.x, mat = blockIdx.y, zc = blockIdx.z;
    int tid = threadIdx.x, lane = tid & 31, wid = tid >> 5;
    sxs[tid] = g_sx[b * CC + tid];
    __syncthreads();
    const float* w = mat ? wk : wq;
    float* outv = mat ? g_ks : g_qs;
#pragma unroll
    for (int i = 0; i < 4; i++) {
        int o = zc * 32 + wid * 4 + i;
        const float* r = w + o * CC;
        float s = 0.f;
#pragma unroll
        for (int j = 0; j < 8; j++) {
            int cidx = lane + 32 * j;
            s += r[cidx] * sxs[cidx];
        }
#pragma unroll
        for (int off = 16; off; off >>= 1) s += __shfl_down_sync(0xFFFFFFFFu, s, off);
        if (lane == 0) outv[b * CC + o] = s;
    }
}

// ---------------- softmax (+ folded cv = A bv) ------------------------------
__global__ void softmax_kernel(const float* __restrict__ bq, const float* __restrict__ bk,
                               const float* __restrict__ bv) {
    int row = blockIdx.x;
    int b = row >> 8, c = row & 255;
    int d = threadIdx.x;
    __shared__ float red[256];
    float v = g_L[(size_t)row * CC + d];
    float bqc = bq[c];
    v += g_qs[b * CC + c] * bk[d] + bqc * g_ks[b * CC + d] + 4096.f * bqc * bk[d];
    v *= 0.0625f;
    red[d] = v;
    __syncthreads();
#pragma unroll
    for (int s = 128; s; s >>= 1) { if (d < s) red[d] = fmaxf(red[d], red[d + s]); __syncthreads(); }
    float m = red[0];
    __syncthreads();
    float e = __expf(v - m);
    red[d] = e;
    __syncthreads();
#pragma unroll
    for (int s = 128; s; s >>= 1) { if (d < s) red[d] += red[d + s]; __syncthreads(); }
    float p = e * (1.0f / red[0]);
    g_L[(size_t)row * CC + d] = p;
    __syncthreads();
    red[d] = p * bv[d];
    __syncthreads();
#pragma unroll
    for (int s = 128; s; s >>= 1) { if (d < s) red[d] += red[d + s]; __syncthreads(); }
    if (d == 0) g_cv[row] = red[0];
}

// ---------------- misc small kernels ----------------------------------------
__global__ void wvt_kernel(const float* __restrict__ wv) {
    int d = blockIdx.x, e = threadIdx.x;
    g_Wvt[e * CC + d] = wv[d * CC + e];
}
__global__ void splitm_kernel() {
    int i = (blockIdx.x * 256 + threadIdx.x) * 4;
    float4 v = *(const float4*)(g_M + i);
    bf16 h[4], l[4];
    split2(v.x, h[0], l[0]); split2(v.y, h[1], l[1]);
    split2(v.z, h[2], l[2]); split2(v.w, h[3], l[3]);
    *(uint2*)(g_Mh + i) = make_uint2(pack2(h[0], h[1]), pack2(h[2], h[3]));
    *(uint2*)(g_Ml + i) = make_uint2(pack2(l[0], l[1]), pack2(l[2], l[3]));
}
__global__ void reduceg_kernel() {
    int i = (blockIdx.x * 256 + threadIdx.x) * 4;
    float4 a = *(const float4*)(g_Gp + i);
    float4 b = *(const float4*)(g_Gp + BB * CC * CC + i);
    *(float4*)(g_G + i) = make_float4(a.x + b.x, a.y + b.y, a.z + b.z, a.w + b.w);
}

// ---------------- launcher ----------------
extern "C" void kernel_launch(void* const* d_in, const int* in_sizes, int n_in,
                              void* d_out, int out_size) {
    const float* x  = (const float*)d_in[0];
    const float* wq = (const float*)d_in[1];
    const float* bq = (const float*)d_in[2];
    const float* wk = (const float*)d_in[3];
    const float* bk = (const float*)d_in[4];
    const float* wv = (const float*)d_in[5];
    const float* bv = (const float*)d_in[6];
    float* out = (float*)d_out;

    float *pG, *pGp, *pT, *pL, *pM, *pWvt, *pcv;
    bf16 *pyh, *pyl, *pxth, *pxtl, *pMh, *pMl;
    cudaGetSymbolAddress((void**)&pG, g_G);
    cudaGetSymbolAddress((void**)&pGp, g_Gp);
    cudaGetSymbolAddress((void**)&pT, g_T);
    cudaGetSymbolAddress((void**)&pL, g_L);
    cudaGetSymbolAddress((void**)&pM, g_M);
    cudaGetSymbolAddress((void**)&pWvt, g_Wvt);
    cudaGetSymbolAddress((void**)&pcv, g_cv);
    cudaGetSymbolAddress((void**)&pyh, g_yh);
    cudaGetSymbolAddress((void**)&pyl, g_yl);
    cudaGetSymbolAddress((void**)&pxth, g_xth);
    cudaGetSymbolAddress((void**)&pxtl, g_xtl);
    cudaGetSymbolAddress((void**)&pMh, g_Mh);
    cudaGetSymbolAddress((void**)&pMl, g_Ml);

    const int SMEMB = 2 * STG_US * 2;  // 81920 bytes
    cudaFuncSetAttribute(bgemm<0>, cudaFuncAttributeMaxDynamicSharedMemorySize, SMEMB);
    cudaFuncSetAttribute(bgemm<1>, cudaFuncAttributeMaxDynamicSharedMemorySize, SMEMB);

    const long CN = (long)CC * NPIX;
    const long C2 = (long)CC * CC;

    splitx_kernel<<<dim3(128, 8, 16), 256>>>(x);
    rowsum_kernel<<<512, 256>>>(x);
    wvt_kernel<<<256, 256>>>(wv);
    proj_sums<<<dim3(16, 2, 8), 256>>>(wq, wk);
    // G partials: y y^T bf16, split-K 2 (z = kc*16 + b), T = 64 iters
    bgemm<0><<<dim3(2, 2, 32), 256, SMEMB>>>(pyh, pyl, pyh, pyl, pGp,
                                             64, NPIX, NPIX, CN, CN, C2, 15, 4, 2048,
                                             nullptr, nullptr, nullptr);
    reduceg_kernel<<<1024, 256>>>();
    // T = Wq G ; L = T Wk^T ; softmax(+cv) ; M = A Wv^T
    mgemm<<<dim3(2, 2, 16), 256>>>(wq, pG, pT, CC, CC, CC, 0, C2, C2);
    mgemm<<<dim3(2, 2, 16), 256>>>(pT, wk, pL, CC, CC, CC, C2, 0, C2);
    softmax_kernel<<<4096, 256>>>(bq, bk, bv);
    mgemm<<<dim3(2, 2, 16), 256>>>(pL, pWvt, pM, CC, CC, CC, C2, 0, C2);
    splitm_kernel<<<1024, 256>>>();
    // out = x + M x + cv  (A = M hi/lo [c][d], B = x^T hi/lo [n][d], T = 8)
    bgemm<1><<<dim3(32, 2, 16), 256, SMEMB>>>(pMh, pMl, pxth, pxtl, nullptr,
                                              8, CC, CC, C2, (long)NPIX * CC, 0, 255, 8, 0,
                                              x, pcv, out);
}

// round 10
// speedup vs baseline: 2.1616x; 1.0480x over previous
#include <cuda_runtime.h>
#include <cuda_bf16.h>

#define BB 16
#define CC 256
#define NPIX 4096
typedef __nv_bfloat16 bf16;
typedef unsigned int u32;
typedef unsigned short u16;

// ---------------- scratch (device globals) ----------------
__device__ float g_G[BB * CC * CC];
__device__ float g_Gp[2 * BB * CC * CC];
__device__ float g_T[BB * CC * CC];
__device__ float g_L[BB * CC * CC];
__device__ float g_M[BB * CC * CC];
__device__ float g_Wvt[CC * CC];
__device__ float g_sxp[BB * CC * 128];
__device__ float g_sx[BB * CC], g_qs[BB * CC], g_ks[BB * CC], g_cv[BB * CC];
__device__ __align__(16) bf16 g_yh[(size_t)BB * CC * NPIX];
__device__ __align__(16) bf16 g_yl[(size_t)BB * CC * NPIX];
__device__ __align__(16) bf16 g_xth[(size_t)BB * NPIX * CC];
__device__ __align__(16) bf16 g_xtl[(size_t)BB * NPIX * CC];
__device__ __align__(16) bf16 g_Mh[BB * CC * CC];
__device__ __align__(16) bf16 g_Ml[BB * CC * CC];

// ---------------- helpers ----------------
__device__ __forceinline__ void split2(float f, bf16& h, bf16& l) {
    h = __float2bfloat16(f);
    l = __float2bfloat16(f - __bfloat162float(h));
}
__device__ __forceinline__ u32 pack2(bf16 a, bf16 b) {
    return (u32)__bfloat16_as_ushort(a) | ((u32)__bfloat16_as_ushort(b) << 16);
}
__device__ __forceinline__ void cvt4(float4 v, uint2& h, uint2& l) {
    bf16 h0, l0, h1, l1, h2, l2, h3, l3;
    split2(v.x, h0, l0); split2(v.y, h1, l1);
    split2(v.z, h2, l2); split2(v.w, h3, l3);
    h = make_uint2(pack2(h0, h1), pack2(h2, h3));
    l = make_uint2(pack2(l0, l1), pack2(l2, l3));
}
__device__ __forceinline__ void mma16816(float* c, const u32* a, const u32* b) {
    asm volatile(
        "mma.sync.aligned.m16n8k16.row.col.f32.bf16.bf16.f32 "
        "{%0,%1,%2,%3}, {%4,%5,%6,%7}, {%8,%9}, {%0,%1,%2,%3};"
        : "+f"(c[0]), "+f"(c[1]), "+f"(c[2]), "+f"(c[3])
        : "r"(a[0]), "r"(a[1]), "r"(a[2]), "r"(a[3]), "r"(b[0]), "r"(b[1]));
}
__device__ __forceinline__ void cp16(u32 saddr, const void* g) {
    asm volatile("cp.async.ca.shared.global [%0], [%1], 16;" :: "r"(saddr), "l"(g));
}
__device__ __forceinline__ float b2f(u16 v) {
    return __bfloat162float(__ushort_as_bfloat16(v));
}

// ---------------- 2-stage cp.async bf16 hi/lo GEMM --------------------------
// A: bf16 hi/lo rows = M (ld lda). B: bf16 hi/lo rows = N (ld ldb). K-major.
// EPI 0: fp32 C at z*sC (ldc=CC). EPI 1: out = x + D + cv, residual taken
//        from the smem B tile (B = x^T) during the matching k-iteration.
#define STG_US 20480  // u16 per stage: 4 tiles * 128*40
template <int EPI>
__global__ void __launch_bounds__(256, 1) bgemm(
    const bf16* __restrict__ Ahg, const bf16* __restrict__ Alg,
    const bf16* __restrict__ Bhg, const bf16* __restrict__ Blg,
    float* __restrict__ C, int T, int lda, int ldb, long sA, long sB, long sC,
    int bmask, int sb, int kps,
    const float* __restrict__ cvv, float* __restrict__ outp)
{
    extern __shared__ __align__(16) u16 smp[];
    int tid = threadIdx.x, lane = tid & 31, wid = tid >> 5;
    int wm = wid >> 2, wn = wid & 3;
    int bx = blockIdx.x, by = blockIdx.y, z = blockIdx.z;
    int b = z & bmask;
    int kbase = (z >> sb) * kps;

    const bf16* Abh = Ahg + (size_t)b * sA + (size_t)(by * 128) * lda + kbase;
    const bf16* Abl = Alg + (size_t)b * sA + (size_t)(by * 128) * lda + kbase;
    const bf16* Bbh = Bhg + (size_t)b * sB + (size_t)(bx * 128) * ldb + kbase;
    const bf16* Bbl = Blg + (size_t)b * sB + (size_t)(bx * 128) * ldb + kbase;

    u32 sbase;
    asm("{ .reg .u64 t; cvta.to.shared.u64 t, %1; cvt.u32.u64 %0, t; }"
        : "=r"(sbase) : "l"(smp));

    auto PREF = [&](int t) {
        if (t < T) {
            int k0 = t * 32, st = t & 1;
            u32 s0 = sbase + (u32)(st * STG_US) * 2;
#pragma unroll
            for (int j = 0; j < 2; j++) {
                int idx = tid * 2 + j;          // 0..511
                int r = idx >> 2, c8 = (idx & 3) * 8;
                u32 off = (u32)(r * 40 + c8) * 2;
                cp16(s0 + off,         Abh + (size_t)r * lda + k0 + c8);
                cp16(s0 + off + 10240, Abl + (size_t)r * lda + k0 + c8);
                cp16(s0 + off + 20480, Bbh + (size_t)r * ldb + k0 + c8);
                cp16(s0 + off + 30720, Bbl + (size_t)r * ldb + k0 + c8);
            }
        }
        asm volatile("cp.async.commit_group;" ::: "memory");
    };

    float acc[4][4][4] = {};
    PREF(0);
    for (int t = 0; t < T; t++) {
        PREF(t + 1);
        asm volatile("cp.async.wait_group 1;" ::: "memory");
        __syncthreads();
        int st = t & 1;
        u16 (*Ah)[40] = (u16(*)[40])(smp + st * STG_US);
        u16 (*Al)[40] = (u16(*)[40])(smp + st * STG_US + 5120);
        u16 (*Bh)[40] = (u16(*)[40])(smp + st * STG_US + 10240);
        u16 (*Bl)[40] = (u16(*)[40])(smp + st * STG_US + 15360);
#pragma unroll
        for (int kc = 0; kc < 32; kc += 16) {
            int kk = kc + (lane & 3) * 2;
            u32 afh[4][4], afl[4][4], bfh[4][2], bfl[4][2];
#pragma unroll
            for (int mf = 0; mf < 4; mf++) {
                int r0 = wm * 64 + mf * 16 + (lane >> 2);
                afh[mf][0] = *(const u32*)&Ah[r0][kk];
                afh[mf][1] = *(const u32*)&Ah[r0 + 8][kk];
                afh[mf][2] = *(const u32*)&Ah[r0][kk + 8];
                afh[mf][3] = *(const u32*)&Ah[r0 + 8][kk + 8];
                afl[mf][0] = *(const u32*)&Al[r0][kk];
                afl[mf][1] = *(const u32*)&Al[r0 + 8][kk];
                afl[mf][2] = *(const u32*)&Al[r0][kk + 8];
                afl[mf][3] = *(const u32*)&Al[r0 + 8][kk + 8];
            }
#pragma unroll
            for (int nf = 0; nf < 4; nf++) {
                int c0 = wn * 32 + nf * 8 + (lane >> 2);
                bfh[nf][0] = *(const u32*)&Bh[c0][kk];
                bfh[nf][1] = *(const u32*)&Bh[c0][kk + 8];
                bfl[nf][0] = *(const u32*)&Bl[c0][kk];
                bfl[nf][1] = *(const u32*)&Bl[c0][kk + 8];
            }
#pragma unroll
            for (int mf = 0; mf < 4; mf++)
#pragma unroll
                for (int nf = 0; nf < 4; nf++) {
                    mma16816(acc[mf][nf], afh[mf], bfh[nf]);
                    mma16816(acc[mf][nf], afh[mf], bfl[nf]);
                    mma16816(acc[mf][nf], afl[mf], bfh[nf]);
                }
        }
        if (EPI == 1) {
            // residual: x[rg, cg] = xt[cg][rg] lives in this B tile when the
            // current c-chunk t covers rg. t_res(mf) = by*4 + wm*2 + (mf>>1).
            int tb = by * 4 + wm * 2;
#pragma unroll
            for (int mf = 0; mf < 4; mf++) {
                if (t == tb + (mf >> 1)) {
                    int kkr = (mf & 1) * 16 + (lane >> 2);
#pragma unroll
                    for (int nf = 0; nf < 4; nf++) {
                        int c0 = wn * 32 + nf * 8 + (lane & 3) * 2;
                        acc[mf][nf][0] += b2f(Bh[c0][kkr]) + b2f(Bl[c0][kkr]);
                        acc[mf][nf][1] += b2f(Bh[c0 + 1][kkr]) + b2f(Bl[c0 + 1][kkr]);
                        acc[mf][nf][2] += b2f(Bh[c0][kkr + 8]) + b2f(Bl[c0][kkr + 8]);
                        acc[mf][nf][3] += b2f(Bh[c0 + 1][kkr + 8]) + b2f(Bl[c0 + 1][kkr + 8]);
                    }
                }
            }
        }
        __syncthreads();
    }

#pragma unroll
    for (int mf = 0; mf < 4; mf++) {
        int rg = by * 128 + wm * 64 + mf * 16 + (lane >> 2);
#pragma unroll
        for (int nf = 0; nf < 4; nf++) {
            int cg = bx * 128 + wn * 32 + nf * 8 + (lane & 3) * 2;
            float* a = acc[mf][nf];
            if (EPI == 0) {
                float* p = C + (size_t)z * sC + (size_t)rg * CC + cg;
                *(float2*)p = make_float2(a[0], a[1]);
                *(float2*)(p + 8 * CC) = make_float2(a[2], a[3]);
            } else {
                size_t o0 = (size_t)b * CC * NPIX + (size_t)rg * NPIX + cg;
                size_t o1 = o0 + 8 * NPIX;
                float cv0 = cvv[b * CC + rg];
                float cv1 = cvv[b * CC + rg + 8];
                *(float2*)(outp + o0) = make_float2(a[0] + cv0, a[1] + cv0);
                *(float2*)(outp + o1) = make_float2(a[2] + cv1, a[3] + cv1);
            }
        }
    }
}

// ---------------- fp32-input hi/lo mma GEMM (small GEMMs; proven) -----------
__global__ void __launch_bounds__(256, 1) mgemm(
    const float* __restrict__ A, const float* __restrict__ B, float* __restrict__ C,
    int K, int lda, int ldb, long sA, long sB, long sC)
{
    __shared__ __align__(16) u16 Ah[128][40], Al[128][40];
    __shared__ __align__(16) u16 Bh[128][40], Bl[128][40];
    int tid = threadIdx.x, lane = tid & 31, wid = tid >> 5;
    int wm = wid >> 2, wn = wid & 3;
    int bx = blockIdx.x, by = blockIdx.y, b = blockIdx.z;
    const float* Ab = A + (size_t)b * sA + (size_t)(by * 128) * lda;
    const float* Bb = B + (size_t)b * sB;
    float acc[4][4][4] = {};
    float4 va[4], vb[4];
    int arow = tid >> 1, acb = (tid & 1) * 16;
    auto LDG = [&](int k0) {
#pragma unroll
        for (int j = 0; j < 4; j++) {
            va[j] = *(const float4*)(Ab + (size_t)arow * lda + k0 + acb + 4 * j);
            vb[j] = *(const float4*)(Bb + (size_t)(bx * 128 + arow) * ldb + k0 + acb + 4 * j);
        }
    };
    auto STS = [&]() {
#pragma unroll
        for (int j = 0; j < 4; j++) {
            uint2 h, l;
            cvt4(va[j], h, l);
            *(uint2*)&Ah[arow][acb + 4 * j] = h;
            *(uint2*)&Al[arow][acb + 4 * j] = l;
            cvt4(vb[j], h, l);
            *(uint2*)&Bh[arow][acb + 4 * j] = h;
            *(uint2*)&Bl[arow][acb + 4 * j] = l;
        }
    };
    int T = K >> 5;
    LDG(0);
    for (int t = 0; t < T; t++) {
        STS();
        __syncthreads();
        if (t + 1 < T) LDG((t + 1) << 5);
#pragma unroll
        for (int kc = 0; kc < 32; kc += 16) {
            int kk = kc + (lane & 3) * 2;
            u32 afh[4][4], afl[4][4], bfh[4][2], bfl[4][2];
#pragma unroll
            for (int mf = 0; mf < 4; mf++) {
                int r0 = wm * 64 + mf * 16 + (lane >> 2);
                afh[mf][0] = *(const u32*)&Ah[r0][kk];
                afh[mf][1] = *(const u32*)&Ah[r0 + 8][kk];
                afh[mf][2] = *(const u32*)&Ah[r0][kk + 8];
                afh[mf][3] = *(const u32*)&Ah[r0 + 8][kk + 8];
                afl[mf][0] = *(const u32*)&Al[r0][kk];
                afl[mf][1] = *(const u32*)&Al[r0 + 8][kk];
                afl[mf][2] = *(const u32*)&Al[r0][kk + 8];
                afl[mf][3] = *(const u32*)&Al[r0 + 8][kk + 8];
            }
#pragma unroll
            for (int nf = 0; nf < 4; nf++) {
                int c0 = wn * 32 + nf * 8 + (lane >> 2);
                bfh[nf][0] = *(const u32*)&Bh[c0][kk];
                bfh[nf][1] = *(const u32*)&Bh[c0][kk + 8];
                bfl[nf][0] = *(const u32*)&Bl[c0][kk];
                bfl[nf][1] = *(const u32*)&Bl[c0][kk + 8];
            }
#pragma unroll
            for (int mf = 0; mf < 4; mf++)
#pragma unroll
                for (int nf = 0; nf < 4; nf++) {
                    mma16816(acc[mf][nf], afh[mf], bfh[nf]);
                    mma16816(acc[mf][nf], afh[mf], bfl[nf]);
                    mma16816(acc[mf][nf], afl[mf], bfh[nf]);
                }
        }
        __syncthreads();
    }
#pragma unroll
    for (int mf = 0; mf < 4; mf++) {
        int rg = by * 128 + wm * 64 + mf * 16 + (lane >> 2);
#pragma unroll
        for (int nf = 0; nf < 4; nf++) {
            int cg = bx * 128 + wn * 32 + nf * 8 + (lane & 3) * 2;
            float* a = acc[mf][nf];
            float* p = C + (size_t)b * sC + (size_t)rg * CC + cg;
            *(float2*)p = make_float2(a[0], a[1]);
            *(float2*)(p + 8 * CC) = make_float2(a[2], a[3]);
        }
    }
}

// ---------------- split x -> yh/yl, xth/xtl, and row-sum partials -----------
__global__ void splitx_kernel(const float* __restrict__ x) {
    __shared__ u32 st[32][33];
    int b = blockIdx.z, c0 = blockIdx.y * 32, n0 = blockIdx.x * 32;
    int tid = threadIdx.x;
    int c = tid >> 3, n4 = (tid & 7) * 4;
    float4 v = *(const float4*)(x + ((size_t)(b * CC + c0 + c)) * NPIX + n0 + n4);
    bf16 h[4], l[4];
    split2(v.x, h[0], l[0]); split2(v.y, h[1], l[1]);
    split2(v.z, h[2], l[2]); split2(v.w, h[3], l[3]);
    size_t yo = ((size_t)(b * CC + c0 + c)) * NPIX + n0 + n4;
    *(uint2*)(g_yh + yo) = make_uint2(pack2(h[0], h[1]), pack2(h[2], h[3]));
    *(uint2*)(g_yl + yo) = make_uint2(pack2(l[0], l[1]), pack2(l[2], l[3]));
    // deterministic partial row sum over this block's 32 n-values
    float ps = (v.x + v.y) + (v.z + v.w);
#pragma unroll
    for (int o = 4; o; o >>= 1) ps += __shfl_down_sync(0xFFFFFFFFu, ps, o, 8);
    if ((tid & 7) == 0)
        g_sxp[(size_t)(b * CC + c0 + c) * 128 + blockIdx.x] = ps;
#pragma unroll
    for (int j = 0; j < 4; j++)
        st[c][n4 + j] = (u32)__bfloat16_as_ushort(h[j]) | ((u32)__bfloat16_as_ushort(l[j]) << 16);
    __syncthreads();
    int n = tid >> 3, c4 = (tid & 7) * 4;
    bf16 th[4], tl[4];
#pragma unroll
    for (int j = 0; j < 4; j++) {
        u32 w = st[c4 + j][n];
        th[j] = __ushort_as_bfloat16((u16)(w & 0xFFFF));
        tl[j] = __ushort_as_bfloat16((u16)(w >> 16));
    }
    size_t to = ((size_t)b * NPIX + n0 + n) * CC + c0 + c4;
    *(uint2*)(g_xth + to) = make_uint2(pack2(th[0], th[1]), pack2(th[2], th[3]));
    *(uint2*)(g_xtl + to) = make_uint2(pack2(tl[0], tl[1]), pack2(tl[2], tl[3]));
}

// ---------------- reduce row-sum partials: warp per row ---------------------
__global__ void reduce_sx_kernel() {
    int row = blockIdx.x * 8 + (threadIdx.x >> 5);
    int lane = threadIdx.x & 31;
    const float* p = g_sxp + (size_t)row * 128;
    float s = 0.f;
#pragma unroll
    for (int j = 0; j < 4; j++) s += p[lane + 32 * j];
#pragma unroll
    for (int o = 16; o; o >>= 1) s += __shfl_down_sync(0xFFFFFFFFu, s, o);
    if (lane == 0) g_sx[row] = s;
}

// ---------------- qs/ks: warp per output, grid-parallel ---------------------
__global__ void proj_sums(const float* __restrict__ wq, const float* __restrict__ wk) {
    __shared__ float sxs[CC];
    int b = blockIdx.x, mat = blockIdx.y, zc = blockIdx.z;
    int tid = threadIdx.x, lane = tid & 31, wid = tid >> 5;
    sxs[tid] = g_sx[b * CC + tid];
    __syncthreads();
    const float* w = mat ? wk : wq;
    float* outv = mat ? g_ks : g_qs;
#pragma unroll
    for (int i = 0; i < 4; i++) {
        int o = zc * 32 + wid * 4 + i;
        const float* r = w + o * CC;
        float s = 0.f;
#pragma unroll
        for (int j = 0; j < 8; j++) {
            int cidx = lane + 32 * j;
            s += r[cidx] * sxs[cidx];
        }
#pragma unroll
        for (int off = 16; off; off >>= 1) s += __shfl_down_sync(0xFFFFFFFFu, s, off);
        if (lane == 0) outv[b * CC + o] = s;
    }
}

// ---------------- softmax (+ folded cv = A bv) ------------------------------
__global__ void softmax_kernel(const float* __restrict__ bq, const float* __restrict__ bk,
                               const float* __restrict__ bv) {
    int row = blockIdx.x;
    int b = row >> 8, c = row & 255;
    int d = threadIdx.x;
    __shared__ float red[256];
    float v = g_L[(size_t)row * CC + d];
    float bqc = bq[c];
    v += g_qs[b * CC + c] * bk[d] + bqc * g_ks[b * CC + d] + 4096.f * bqc * bk[d];
    v *= 0.0625f;
    red[d] = v;
    __syncthreads();
#pragma unroll
    for (int s = 128; s; s >>= 1) { if (d < s) red[d] = fmaxf(red[d], red[d + s]); __syncthreads(); }
    float m = red[0];
    __syncthreads();
    float e = __expf(v - m);
    red[d] = e;
    __syncthreads();
#pragma unroll
    for (int s = 128; s; s >>= 1) { if (d < s) red[d] += red[d + s]; __syncthreads(); }
    float p = e * (1.0f / red[0]);
    g_L[(size_t)row * CC + d] = p;
    __syncthreads();
    red[d] = p * bv[d];
    __syncthreads();
#pragma unroll
    for (int s = 128; s; s >>= 1) { if (d < s) red[d] += red[d + s]; __syncthreads(); }
    if (d == 0) g_cv[row] = red[0];
}

// ---------------- misc small kernels ----------------------------------------
__global__ void wvt_kernel(const float* __restrict__ wv) {
    int d = blockIdx.x, e = threadIdx.x;
    g_Wvt[e * CC + d] = wv[d * CC + e];
}
__global__ void splitm_kernel() {
    int i = (blockIdx.x * 256 + threadIdx.x) * 4;
    float4 v = *(const float4*)(g_M + i);
    bf16 h[4], l[4];
    split2(v.x, h[0], l[0]); split2(v.y, h[1], l[1]);
    split2(v.z, h[2], l[2]); split2(v.w, h[3], l[3]);
    *(uint2*)(g_Mh + i) = make_uint2(pack2(h[0], h[1]), pack2(h[2], h[3]));
    *(uint2*)(g_Ml + i) = make_uint2(pack2(l[0], l[1]), pack2(l[2], l[3]));
}
__global__ void reduceg_kernel() {
    int i = (blockIdx.x * 256 + threadIdx.x) * 4;
    float4 a = *(const float4*)(g_Gp + i);
    float4 b = *(const float4*)(g_Gp + BB * CC * CC + i);
    *(float4*)(g_G + i) = make_float4(a.x + b.x, a.y + b.y, a.z + b.z, a.w + b.w);
}

// ---------------- launcher ----------------
extern "C" void kernel_launch(void* const* d_in, const int* in_sizes, int n_in,
                              void* d_out, int out_size) {
    const float* x  = (const float*)d_in[0];
    const float* wq = (const float*)d_in[1];
    const float* bq = (const float*)d_in[2];
    const float* wk = (const float*)d_in[3];
    const float* bk = (const float*)d_in[4];
    const float* wv = (const float*)d_in[5];
    const float* bv = (const float*)d_in[6];
    float* out = (float*)d_out;

    float *pG, *pGp, *pT, *pL, *pM, *pWvt, *pcv;
    bf16 *pyh, *pyl, *pxth, *pxtl, *pMh, *pMl;
    cudaGetSymbolAddress((void**)&pG, g_G);
    cudaGetSymbolAddress((void**)&pGp, g_Gp);
    cudaGetSymbolAddress((void**)&pT, g_T);
    cudaGetSymbolAddress((void**)&pL, g_L);
    cudaGetSymbolAddress((void**)&pM, g_M);
    cudaGetSymbolAddress((void**)&pWvt, g_Wvt);
    cudaGetSymbolAddress((void**)&pcv, g_cv);
    cudaGetSymbolAddress((void**)&pyh, g_yh);
    cudaGetSymbolAddress((void**)&pyl, g_yl);
    cudaGetSymbolAddress((void**)&pxth, g_xth);
    cudaGetSymbolAddress((void**)&pxtl, g_xtl);
    cudaGetSymbolAddress((void**)&pMh, g_Mh);
    cudaGetSymbolAddress((void**)&pMl, g_Ml);

    const int SMEMB = 2 * STG_US * 2;  // 81920 bytes
    cudaFuncSetAttribute(bgemm<0>, cudaFuncAttributeMaxDynamicSharedMemorySize, SMEMB);
    cudaFuncSetAttribute(bgemm<1>, cudaFuncAttributeMaxDynamicSharedMemorySize, SMEMB);

    const long CN = (long)CC * NPIX;
    const long C2 = (long)CC * CC;

    splitx_kernel<<<dim3(128, 8, 16), 256>>>(x);
    reduce_sx_kernel<<<512, 256>>>();
    wvt_kernel<<<256, 256>>>(wv);
    proj_sums<<<dim3(16, 2, 8), 256>>>(wq, wk);
    // G partials: y y^T bf16, split-K 2 (z = kc*16 + b), T = 64 iters
    bgemm<0><<<dim3(2, 2, 32), 256, SMEMB>>>(pyh, pyl, pyh, pyl, pGp,
                                             64, NPIX, NPIX, CN, CN, C2, 15, 4, 2048,
                                             nullptr, nullptr);
    reduceg_kernel<<<1024, 256>>>();
    // T = Wq G ; L = T Wk^T ; softmax(+cv) ; M = A Wv^T
    mgemm<<<dim3(2, 2, 16), 256>>>(wq, pG, pT, CC, CC, CC, 0, C2, C2);
    mgemm<<<dim3(2, 2, 16), 256>>>(pT, wk, pL, CC, CC, CC, C2, 0, C2);
    softmax_kernel<<<4096, 256>>>(bq, bk, bv);
    mgemm<<<dim3(2, 2, 16), 256>>>(pL, pWvt, pM, CC, CC, CC, C2, 0, C2);
    splitm_kernel<<<1024, 256>>>();
    // out = x + M x + cv  (A = M hi/lo [c][d], B = x^T hi/lo [n][d], T = 8)
    bgemm<1><<<dim3(32, 2, 16), 256, SMEMB>>>(pMh, pMl, pxth, pxtl, nullptr,
                                              8, CC, CC, C2, (long)NPIX * CC, 0, 255, 8, 0,
                                              pcv, out);
}

// round 12
// speedup vs baseline: 2.3745x; 1.0985x over previous
#include <cuda_runtime.h>
#include <cuda_bf16.h>

#define BB 16
#define CC 256
#define NPIX 4096
typedef __nv_bfloat16 bf16;
typedef unsigned int u32;
typedef unsigned short u16;

// ---------------- scratch (device globals) ----------------
__device__ float g_G[BB * CC * CC];
__device__ float g_Gp[3 * BB * CC * CC];
__device__ float g_T[BB * CC * CC];
__device__ float g_L[BB * CC * CC];
__device__ float g_Wvt[CC * CC];
__device__ float g_sxp[BB * CC * 128];
__device__ float g_sx[BB * CC], g_qs[BB * CC], g_ks[BB * CC], g_cv[BB * CC];
__device__ __align__(16) bf16 g_yh[(size_t)BB * CC * NPIX];
__device__ __align__(16) bf16 g_yl[(size_t)BB * CC * NPIX];
__device__ __align__(16) bf16 g_xth[(size_t)BB * NPIX * CC];
__device__ __align__(16) bf16 g_xtl[(size_t)BB * NPIX * CC];
__device__ __align__(16) bf16 g_Mh[BB * CC * CC];
__device__ __align__(16) bf16 g_Ml[BB * CC * CC];

// ---------------- helpers ----------------
__device__ __forceinline__ void split2(float f, bf16& h, bf16& l) {
    h = __float2bfloat16(f);
    l = __float2bfloat16(f - __bfloat162float(h));
}
__device__ __forceinline__ u32 pack2(bf16 a, bf16 b) {
    return (u32)__bfloat16_as_ushort(a) | ((u32)__bfloat16_as_ushort(b) << 16);
}
__device__ __forceinline__ void cvt4(float4 v, uint2& h, uint2& l) {
    bf16 h0, l0, h1, l1, h2, l2, h3, l3;
    split2(v.x, h0, l0); split2(v.y, h1, l1);
    split2(v.z, h2, l2); split2(v.w, h3, l3);
    h = make_uint2(pack2(h0, h1), pack2(h2, h3));
    l = make_uint2(pack2(l0, l1), pack2(l2, l3));
}
__device__ __forceinline__ void mma16816(float* c, const u32* a, const u32* b) {
    asm volatile(
        "mma.sync.aligned.m16n8k16.row.col.f32.bf16.bf16.f32 "
        "{%0,%1,%2,%3}, {%4,%5,%6,%7}, {%8,%9}, {%0,%1,%2,%3};"
        : "+f"(c[0]), "+f"(c[1]), "+f"(c[2]), "+f"(c[3])
        : "r"(a[0]), "r"(a[1]), "r"(a[2]), "r"(a[3]), "r"(b[0]), "r"(b[1]));
}
__device__ __forceinline__ void cp16(u32 saddr, const void* g) {
    asm volatile("cp.async.ca.shared.global [%0], [%1], 16;" :: "r"(saddr), "l"(g));
}
__device__ __forceinline__ float b2f(u16 v) {
    return __bfloat162float(__ushort_as_bfloat16(v));
}

// ---------------- 2-stage cp.async bf16 hi/lo GEMM --------------------------
// GSYM=1: symmetric G schedule — blockIdx.x = triangle tile {(0,0),(1,0),(1,1)},
//         blockIdx.y = split-K chunk (43/43/42 iters), diag tiles alias B=A.
// EPI 0: fp32 C at zout*sC (ldc=CC). EPI 1: out = D + cv (+x residual from B tile).
#define STG_US 20480  // u16 per stage: 4 tiles * 128*40
template <int EPI, int GSYM>
__global__ void __launch_bounds__(256, 1) bgemm(
    const bf16* __restrict__ Ahg, const bf16* __restrict__ Alg,
    const bf16* __restrict__ Bhg, const bf16* __restrict__ Blg,
    float* __restrict__ C, int T, int lda, int ldb, long sA, long sB, long sC,
    int bmask, int sb, int kps,
    const float* __restrict__ cvv, float* __restrict__ outp)
{
    extern __shared__ __align__(16) u16 smp[];
    int tid = threadIdx.x, lane = tid & 31, wid = tid >> 5;
    int wm = wid >> 2, wn = wid & 3;
    int bx, by, b, kbase, Titer, zout;
    if (GSYM) {
        int t = blockIdx.x;
        by = (t + 1) >> 1; bx = t >> 1;          // {0:(0,0),1:(1,0),2:(1,1)}
        int kc = blockIdx.y;
        b = blockIdx.z;
        kbase = kc * 1376;                       // 43 iters * 32
        Titer = (kc == 2) ? 42 : 43;
        zout = kc * 16 + b;
    } else {
        bx = blockIdx.x; by = blockIdx.y;
        int z = blockIdx.z;
        b = z & bmask;
        kbase = (z >> sb) * kps;
        Titer = T;
        zout = z;
    }
    bool diag = GSYM && (bx == by);

    const bf16* Abh = Ahg + (size_t)b * sA + (size_t)(by * 128) * lda + kbase;
    const bf16* Abl = Alg + (size_t)b * sA + (size_t)(by * 128) * lda + kbase;
    const bf16* Bbh = Bhg + (size_t)b * sB + (size_t)(bx * 128) * ldb + kbase;
    const bf16* Bbl = Blg + (size_t)b * sB + (size_t)(bx * 128) * ldb + kbase;

    u32 sbase;
    asm("{ .reg .u64 t; cvta.to.shared.u64 t, %1; cvt.u32.u64 %0, t; }"
        : "=r"(sbase) : "l"(smp));

    auto PREF = [&](int t) {
        if (t < Titer) {
            int k0 = t * 32, st = t & 1;
            u32 s0 = sbase + (u32)(st * STG_US) * 2;
#pragma unroll
            for (int j = 0; j < 2; j++) {
                int idx = tid * 2 + j;          // 0..511
                int r = idx >> 2, c8 = (idx & 3) * 8;
                u32 off = (u32)(r * 40 + c8) * 2;
                cp16(s0 + off,         Abh + (size_t)r * lda + k0 + c8);
                cp16(s0 + off + 10240, Abl + (size_t)r * lda + k0 + c8);
                if (!diag) {
                    cp16(s0 + off + 20480, Bbh + (size_t)r * ldb + k0 + c8);
                    cp16(s0 + off + 30720, Bbl + (size_t)r * ldb + k0 + c8);
                }
            }
        }
        asm volatile("cp.async.commit_group;" ::: "memory");
    };

    float acc[4][4][4] = {};
    PREF(0);
    for (int t = 0; t < Titer; t++) {
        PREF(t + 1);
        asm volatile("cp.async.wait_group 1;" ::: "memory");
        __syncthreads();
        int st = t & 1;
        u16 (*Ah)[40] = (u16(*)[40])(smp + st * STG_US);
        u16 (*Al)[40] = (u16(*)[40])(smp + st * STG_US + 5120);
        u16 (*Bh)[40] = diag ? Ah : (u16(*)[40])(smp + st * STG_US + 10240);
        u16 (*Bl)[40] = diag ? Al : (u16(*)[40])(smp + st * STG_US + 15360);
#pragma unroll
        for (int kc = 0; kc < 32; kc += 16) {
            int kk = kc + (lane & 3) * 2;
            u32 afh[4][4], afl[4][4], bfh[4][2], bfl[4][2];
#pragma unroll
            for (int mf = 0; mf < 4; mf++) {
                int r0 = wm * 64 + mf * 16 + (lane >> 2);
                afh[mf][0] = *(const u32*)&Ah[r0][kk];
                afh[mf][1] = *(const u32*)&Ah[r0 + 8][kk];
                afh[mf][2] = *(const u32*)&Ah[r0][kk + 8];
                afh[mf][3] = *(const u32*)&Ah[r0 + 8][kk + 8];
                afl[mf][0] = *(const u32*)&Al[r0][kk];
                afl[mf][1] = *(const u32*)&Al[r0 + 8][kk];
                afl[mf][2] = *(const u32*)&Al[r0][kk + 8];
                afl[mf][3] = *(const u32*)&Al[r0 + 8][kk + 8];
            }
#pragma unroll
            for (int nf = 0; nf < 4; nf++) {
                int c0 = wn * 32 + nf * 8 + (lane >> 2);
                bfh[nf][0] = *(const u32*)&Bh[c0][kk];
                bfh[nf][1] = *(const u32*)&Bh[c0][kk + 8];
                bfl[nf][0] = *(const u32*)&Bl[c0][kk];
                bfl[nf][1] = *(const u32*)&Bl[c0][kk + 8];
            }
#pragma unroll
            for (int mf = 0; mf < 4; mf++)
#pragma unroll
                for (int nf = 0; nf < 4; nf++) {
                    mma16816(acc[mf][nf], afh[mf], bfh[nf]);
                    mma16816(acc[mf][nf], afh[mf], bfl[nf]);
                    mma16816(acc[mf][nf], afl[mf], bfh[nf]);
                }
        }
        if (EPI == 1) {
            // residual: x[rg, cg] = xt[cg][rg] lives in this B tile when the
            // current c-chunk t covers rg. t_res(mf) = by*4 + wm*2 + (mf>>1).
            int tb = by * 4 + wm * 2;
#pragma unroll
            for (int mf = 0; mf < 4; mf++) {
                if (t == tb + (mf >> 1)) {
                    int kkr = (mf & 1) * 16 + (lane >> 2);
#pragma unroll
                    for (int nf = 0; nf < 4; nf++) {
                        int c0 = wn * 32 + nf * 8 + (lane & 3) * 2;
                        acc[mf][nf][0] += b2f(Bh[c0][kkr]) + b2f(Bl[c0][kkr]);
                        acc[mf][nf][1] += b2f(Bh[c0 + 1][kkr]) + b2f(Bl[c0 + 1][kkr]);
                        acc[mf][nf][2] += b2f(Bh[c0][kkr + 8]) + b2f(Bl[c0][kkr + 8]);
                        acc[mf][nf][3] += b2f(Bh[c0 + 1][kkr + 8]) + b2f(Bl[c0 + 1][kkr + 8]);
                    }
                }
            }
        }
        __syncthreads();
    }

#pragma unroll
    for (int mf = 0; mf < 4; mf++) {
        int rg = by * 128 + wm * 64 + mf * 16 + (lane >> 2);
#pragma unroll
        for (int nf = 0; nf < 4; nf++) {
            int cg = bx * 128 + wn * 32 + nf * 8 + (lane & 3) * 2;
            float* a = acc[mf][nf];
            if (EPI == 0) {
                float* p = C + (size_t)zout * sC + (size_t)rg * CC + cg;
                *(float2*)p = make_float2(a[0], a[1]);
                *(float2*)(p + 8 * CC) = make_float2(a[2], a[3]);
            } else {
                size_t o0 = (size_t)b * CC * NPIX + (size_t)rg * NPIX + cg;
                size_t o1 = o0 + 8 * NPIX;
                float cv0 = cvv[b * CC + rg];
                float cv1 = cvv[b * CC + rg + 8];
                *(float2*)(outp + o0) = make_float2(a[0] + cv0, a[1] + cv0);
                *(float2*)(outp + o1) = make_float2(a[2] + cv1, a[3] + cv1);
            }
        }
    }
}

// ---------------- fp32-input hi/lo mma GEMM (small GEMMs; proven) -----------
// EPI 0: fp32 C. EPI 1: write bf16 hi/lo pair into g_Mh/g_Ml (splitm folded).
template <int EPI>
__global__ void __launch_bounds__(256, 1) mgemm(
    const float* __restrict__ A, const float* __restrict__ B, float* __restrict__ C,
    int K, int lda, int ldb, long sA, long sB, long sC)
{
    __shared__ __align__(16) u16 Ah[128][40], Al[128][40];
    __shared__ __align__(16) u16 Bh[128][40], Bl[128][40];
    int tid = threadIdx.x, lane = tid & 31, wid = tid >> 5;
    int wm = wid >> 2, wn = wid & 3;
    int bx = blockIdx.x, by = blockIdx.y, b = blockIdx.z;
    const float* Ab = A + (size_t)b * sA + (size_t)(by * 128) * lda;
    const float* Bb = B + (size_t)b * sB;
    float acc[4][4][4] = {};
    float4 va[4], vb[4];
    int arow = tid >> 1, acb = (tid & 1) * 16;
    auto LDG = [&](int k0) {
#pragma unroll
        for (int j = 0; j < 4; j++) {
            va[j] = *(const float4*)(Ab + (size_t)arow * lda + k0 + acb + 4 * j);
            vb[j] = *(const float4*)(Bb + (size_t)(bx * 128 + arow) * ldb + k0 + acb + 4 * j);
        }
    };
    auto STS = [&]() {
#pragma unroll
        for (int j = 0; j < 4; j++) {
            uint2 h, l;
            cvt4(va[j], h, l);
            *(uint2*)&Ah[arow][acb + 4 * j] = h;
            *(uint2*)&Al[arow][acb + 4 * j] = l;
            cvt4(vb[j], h, l);
            *(uint2*)&Bh[arow][acb + 4 * j] = h;
            *(uint2*)&Bl[arow][acb + 4 * j] = l;
        }
    };
    int T = K >> 5;
    LDG(0);
    for (int t = 0; t < T; t++) {
        STS();
        __syncthreads();
        if (t + 1 < T) LDG((t + 1) << 5);
#pragma unroll
        for (int kc = 0; kc < 32; kc += 16) {
            int kk = kc + (lane & 3) * 2;
            u32 afh[4][4], afl[4][4], bfh[4][2], bfl[4][2];
#pragma unroll
            for (int mf = 0; mf < 4; mf++) {
                int r0 = wm * 64 + mf * 16 + (lane >> 2);
                afh[mf][0] = *(const u32*)&Ah[r0][kk];
                afh[mf][1] = *(const u32*)&Ah[r0 + 8][kk];
                afh[mf][2] = *(const u32*)&Ah[r0][kk + 8];
                afh[mf][3] = *(const u32*)&Ah[r0 + 8][kk + 8];
                afl[mf][0] = *(const u32*)&Al[r0][kk];
                afl[mf][1] = *(const u32*)&Al[r0 + 8][kk];
                afl[mf][2] = *(const u32*)&Al[r0][kk + 8];
                afl[mf][3] = *(const u32*)&Al[r0 + 8][kk + 8];
            }
#pragma unroll
            for (int nf = 0; nf < 4; nf++) {
                int c0 = wn * 32 + nf * 8 + (lane >> 2);
                bfh[nf][0] = *(const u32*)&Bh[c0][kk];
                bfh[nf][1] = *(const u32*)&Bh[c0][kk + 8];
                bfl[nf][0] = *(const u32*)&Bl[c0][kk];
                bfl[nf][1] = *(const u32*)&Bl[c0][kk + 8];
            }
#pragma unroll
            for (int mf = 0; mf < 4; mf++)
#pragma unroll
                for (int nf = 0; nf < 4; nf++) {
                    mma16816(acc[mf][nf], afh[mf], bfh[nf]);
                    mma16816(acc[mf][nf], afh[mf], bfl[nf]);
                    mma16816(acc[mf][nf], afl[mf], bfh[nf]);
                }
        }
        __syncthreads();
    }
#pragma unroll
    for (int mf = 0; mf < 4; mf++) {
        int rg = by * 128 + wm * 64 + mf * 16 + (lane >> 2);
#pragma unroll
        for (int nf = 0; nf < 4; nf++) {
            int cg = bx * 128 + wn * 32 + nf * 8 + (lane & 3) * 2;
            float* a = acc[mf][nf];
            if (EPI == 0) {
                float* p = C + (size_t)b * sC + (size_t)rg * CC + cg;
                *(float2*)p = make_float2(a[0], a[1]);
                *(float2*)(p + 8 * CC) = make_float2(a[2], a[3]);
            } else {
                size_t i0 = (size_t)b * CC * CC + (size_t)rg * CC + cg;
                size_t i1 = i0 + 8 * CC;
                bf16 h0, l0, h1, l1;
                split2(a[0], h0, l0); split2(a[1], h1, l1);
                *(u32*)&g_Mh[i0] = pack2(h0, h1);
                *(u32*)&g_Ml[i0] = pack2(l0, l1);
                split2(a[2], h0, l0); split2(a[3], h1, l1);
                *(u32*)&g_Mh[i1] = pack2(h0, h1);
                *(u32*)&g_Ml[i1] = pack2(l0, l1);
            }
        }
    }
}

// ---------------- split x -> yh/yl, xth/xtl, and row-sum partials -----------
__global__ void splitx_kernel(const float* __restrict__ x) {
    __shared__ u32 st[32][33];
    int b = blockIdx.z, c0 = blockIdx.y * 32, n0 = blockIdx.x * 32;
    int tid = threadIdx.x;
    int c = tid >> 3, n4 = (tid & 7) * 4;
    float4 v = *(const float4*)(x + ((size_t)(b * CC + c0 + c)) * NPIX + n0 + n4);
    bf16 h[4], l[4];
    split2(v.x, h[0], l[0]); split2(v.y, h[1], l[1]);
    split2(v.z, h[2], l[2]); split2(v.w, h[3], l[3]);
    size_t yo = ((size_t)(b * CC + c0 + c)) * NPIX + n0 + n4;
    *(uint2*)(g_yh + yo) = make_uint2(pack2(h[0], h[1]), pack2(h[2], h[3]));
    *(uint2*)(g_yl + yo) = make_uint2(pack2(l[0], l[1]), pack2(l[2], l[3]));
    float ps = (v.x + v.y) + (v.z + v.w);
#pragma unroll
    for (int o = 4; o; o >>= 1) ps += __shfl_down_sync(0xFFFFFFFFu, ps, o, 8);
    if ((tid & 7) == 0)
        g_sxp[(size_t)(b * CC + c0 + c) * 128 + blockIdx.x] = ps;
#pragma unroll
    for (int j = 0; j < 4; j++)
        st[c][n4 + j] = (u32)__bfloat16_as_ushort(h[j]) | ((u32)__bfloat16_as_ushort(l[j]) << 16);
    __syncthreads();
    int n = tid >> 3, c4 = (tid & 7) * 4;
    bf16 th[4], tl[4];
#pragma unroll
    for (int j = 0; j < 4; j++) {
        u32 w = st[c4 + j][n];
        th[j] = __ushort_as_bfloat16((u16)(w & 0xFFFF));
        tl[j] = __ushort_as_bfloat16((u16)(w >> 16));
    }
    size_t to = ((size_t)b * NPIX + n0 + n) * CC + c0 + c4;
    *(uint2*)(g_xth + to) = make_uint2(pack2(th[0], th[1]), pack2(th[2], th[3]));
    *(uint2*)(g_xtl + to) = make_uint2(pack2(tl[0], tl[1]), pack2(tl[2], tl[3]));
}

// ---------------- reduce row-sum partials: warp per row ---------------------
__global__ void reduce_sx_kernel() {
    int row = blockIdx.x * 8 + (threadIdx.x >> 5);
    int lane = threadIdx.x & 31;
    const float* p = g_sxp + (size_t)row * 128;
    float s = 0.f;
#pragma unroll
    for (int j = 0; j < 4; j++) s += p[lane + 32 * j];
#pragma unroll
    for (int o = 16; o; o >>= 1) s += __shfl_down_sync(0xFFFFFFFFu, s, o);
    if (lane == 0) g_sx[row] = s;
}

// ---------------- qs/ks: warp per output, grid-parallel ---------------------
__global__ void proj_sums(const float* __restrict__ wq, const float* __restrict__ wk) {
    __shared__ float sxs[CC];
    int b = blockIdx.x, mat = blockIdx.y, zc = blockIdx.z;
    int tid = threadIdx.x, lane = tid & 31, wid = tid >> 5;
    sxs[tid] = g_sx[b * CC + tid];
    __syncthreads();
    const float* w = mat ? wk : wq;
    float* outv = mat ? g_ks : g_qs;
#pragma unroll
    for (int i = 0; i < 4; i++) {
        int o = zc * 32 + wid * 4 + i;
        const float* r = w + o * CC;
        float s = 0.f;
#pragma unroll
        for (int j = 0; j < 8; j++) {
            int cidx = lane + 32 * j;
            s += r[cidx] * sxs[cidx];
        }
#pragma unroll
        for (int off = 16; off; off >>= 1) s += __shfl_down_sync(0xFFFFFFFFu, s, off);
        if (lane == 0) outv[b * CC + o] = s;
    }
}

// ---------------- softmax (+ folded cv = A bv) ------------------------------
__global__ void softmax_kernel(const float* __restrict__ bq, const float* __restrict__ bk,
                               const float* __restrict__ bv) {
    int row = blockIdx.x;
    int b = row >> 8, c = row & 255;
    int d = threadIdx.x;
    __shared__ float red[256];
    float v = g_L[(size_t)row * CC + d];
    float bqc = bq[c];
    v += g_qs[b * CC + c] * bk[d] + bqc * g_ks[b * CC + d] + 4096.f * bqc * bk[d];
    v *= 0.0625f;
    red[d] = v;
    __syncthreads();
#pragma unroll
    for (int s = 128; s; s >>= 1) { if (d < s) red[d] = fmaxf(red[d], red[d + s]); __syncthreads(); }
    float m = red[0];
    __syncthreads();
    float e = __expf(v - m);
    red[d] = e;
    __syncthreads();
#pragma unroll
    for (int s = 128; s; s >>= 1) { if (d < s) red[d] += red[d + s]; __syncthreads(); }
    float p = e * (1.0f / red[0]);
    g_L[(size_t)row * CC + d] = p;
    __syncthreads();
    red[d] = p * bv[d];
    __syncthreads();
#pragma unroll
    for (int s = 128; s; s >>= 1) { if (d < s) red[d] += red[d + s]; __syncthreads(); }
    if (d == 0) g_cv[row] = red[0];
}

// ---------------- misc small kernels ----------------------------------------
__global__ void wvt_kernel(const float* __restrict__ wv) {
    int d = blockIdx.x, e = threadIdx.x;
    g_Wvt[e * CC + d] = wv[d * CC + e];
}
__global__ void reduceg_kernel() {
    int i = (blockIdx.x * 256 + threadIdx.x) * 4;
    float4 a = *(const float4*)(g_Gp + i);
    float4 b = *(const float4*)(g_Gp + (size_t)BB * CC * CC + i);
    float4 c = *(const float4*)(g_Gp + (size_t)2 * BB * CC * CC + i);
    *(float4*)(g_G + i) = make_float4(a.x + b.x + c.x, a.y + b.y + c.y,
                                      a.z + b.z + c.z, a.w + b.w + c.w);
}
// mirror: G[b][c][128+j] = G[b][128+j][c]  (fills the skipped (0,1) tile)
__global__ void mirror_kernel() {
    __shared__ float s[32][33];
    int b = blockIdx.z;
    int r0 = 128 + blockIdx.y * 32;   // source rows (d)
    int c0 = blockIdx.x * 32;         // source cols (c)
    float* Gb = g_G + (size_t)b * CC * CC;
    int tx = threadIdx.x & 31, ty = threadIdx.x >> 5;
#pragma unroll
    for (int i = ty; i < 32; i += 8)
        s[i][tx] = Gb[(size_t)(r0 + i) * CC + c0 + tx];
    __syncthreads();
#pragma unroll
    for (int i = ty; i < 32; i += 8)
        Gb[(size_t)(c0 + i) * CC + r0 + tx] = s[tx][i];
}

// ---------------- launcher ----------------
extern "C" void kernel_launch(void* const* d_in, const int* in_sizes, int n_in,
                              void* d_out, int out_size) {
    const float* x  = (const float*)d_in[0];
    const float* wq = (const float*)d_in[1];
    const float* bq = (const float*)d_in[2];
    const float* wk = (const float*)d_in[3];
    const float* bk = (const float*)d_in[4];
    const float* wv = (const float*)d_in[5];
    const float* bv = (const float*)d_in[6];
    float* out = (float*)d_out;

    float *pG, *pGp, *pT, *pL, *pWvt, *pcv;
    bf16 *pyh, *pyl, *pxth, *pxtl, *pMh, *pMl;
    cudaGetSymbolAddress((void**)&pG, g_G);
    cudaGetSymbolAddress((void**)&pGp, g_Gp);
    cudaGetSymbolAddress((void**)&pT, g_T);
    cudaGetSymbolAddress((void**)&pL, g_L);
    cudaGetSymbolAddress((void**)&pWvt, g_Wvt);
    cudaGetSymbolAddress((void**)&pcv, g_cv);
    cudaGetSymbolAddress((void**)&pyh, g_yh);
    cudaGetSymbolAddress((void**)&pyl, g_yl);
    cudaGetSymbolAddress((void**)&pxth, g_xth);
    cudaGetSymbolAddress((void**)&pxtl, g_xtl);
    cudaGetSymbolAddress((void**)&pMh, g_Mh);
    cudaGetSymbolAddress((void**)&pMl, g_Ml);

    const int SMEMB = 2 * STG_US * 2;  // 81920 bytes
    cudaFuncSetAttribute((const void*)bgemm<0, 1>, cudaFuncAttributeMaxDynamicSharedMemorySize, SMEMB);
    cudaFuncSetAttribute((const void*)bgemm<1, 0>, cudaFuncAttributeMaxDynamicSharedMemorySize, SMEMB);

    const long CN = (long)CC * NPIX;
    const long C2 = (long)CC * CC;

    splitx_kernel<<<dim3(128, 8, 16), 256>>>(x);
    reduce_sx_kernel<<<512, 256>>>();
    wvt_kernel<<<256, 256>>>(wv);
    proj_sums<<<dim3(16, 2, 8), 256>>>(wq, wk);
    // G partials: y y^T bf16, symmetric triangle tiles x split-K 3
    bgemm<0, 1><<<dim3(3, 3, 16), 256, SMEMB>>>(pyh, pyl, pyh, pyl, pGp,
                                                0, NPIX, NPIX, CN, CN, C2, 0, 0, 0,
                                                nullptr, nullptr);
    reduceg_kernel<<<1024, 256>>>();
    mirror_kernel<<<dim3(4, 4, 16), 256>>>();
    // T = Wq G ; L = T Wk^T ; softmax(+cv) ; M = A Wv^T (bf16 epilogue)
    mgemm<0><<<dim3(2, 2, 16), 256>>>(wq, pG, pT, CC, CC, CC, 0, C2, C2);
    mgemm<0><<<dim3(2, 2, 16), 256>>>(pT, wk, pL, CC, CC, CC, C2, 0, C2);
    softmax_kernel<<<4096, 256>>>(bq, bk, bv);
    mgemm<1><<<dim3(2, 2, 16), 256>>>(pL, pWvt, nullptr, CC, CC, CC, C2, 0, 0);
    // out = x + M x + cv  (A = M hi/lo [c][d], B = x^T hi/lo [n][d], T = 8)
    bgemm<1, 0><<<dim3(32, 2, 16), 256, SMEMB>>>(pMh, pMl, pxth, pxtl, nullptr,
                                                 8, CC, CC, C2, (long)NPIX * CC, 0, 255, 8, 0,
                                                 pcv, out);
}

// round 13
// speedup vs baseline: 2.5132x; 1.0584x over previous
#include <cuda_runtime.h>
#include <cuda_bf16.h>

#define BB 16
#define CC 256
#define NPIX 4096
typedef __nv_bfloat16 bf16;
typedef unsigned int u32;
typedef unsigned short u16;

// ---------------- scratch (device globals) ----------------
__device__ float g_G[BB * CC * CC];
__device__ float g_Gp[3 * BB * CC * CC];
__device__ float g_T[BB * CC * CC];
__device__ float g_L[BB * CC * CC];
__device__ float g_Wvt[CC * CC];
__device__ float g_sxp[BB * CC * 128];
__device__ float g_sx[BB * CC], g_qs[BB * CC], g_ks[BB * CC], g_cv[BB * CC];
__device__ __align__(16) bf16 g_yh[(size_t)BB * CC * NPIX];
__device__ __align__(16) bf16 g_yl[(size_t)BB * CC * NPIX];
__device__ __align__(16) bf16 g_Mh[BB * CC * CC];
__device__ __align__(16) bf16 g_Ml[BB * CC * CC];

// ---------------- helpers ----------------
__device__ __forceinline__ void split2(float f, bf16& h, bf16& l) {
    h = __float2bfloat16(f);
    l = __float2bfloat16(f - __bfloat162float(h));
}
__device__ __forceinline__ u32 pack2(bf16 a, bf16 b) {
    return (u32)__bfloat16_as_ushort(a) | ((u32)__bfloat16_as_ushort(b) << 16);
}
__device__ __forceinline__ void cvt4(float4 v, uint2& h, uint2& l) {
    bf16 h0, l0, h1, l1, h2, l2, h3, l3;
    split2(v.x, h0, l0); split2(v.y, h1, l1);
    split2(v.z, h2, l2); split2(v.w, h3, l3);
    h = make_uint2(pack2(h0, h1), pack2(h2, h3));
    l = make_uint2(pack2(l0, l1), pack2(l2, l3));
}
__device__ __forceinline__ void mma16816(float* c, const u32* a, const u32* b) {
    asm volatile(
        "mma.sync.aligned.m16n8k16.row.col.f32.bf16.bf16.f32 "
        "{%0,%1,%2,%3}, {%4,%5,%6,%7}, {%8,%9}, {%0,%1,%2,%3};"
        : "+f"(c[0]), "+f"(c[1]), "+f"(c[2]), "+f"(c[3])
        : "r"(a[0]), "r"(a[1]), "r"(a[2]), "r"(a[3]), "r"(b[0]), "r"(b[1]));
}
__device__ __forceinline__ void cp16(u32 saddr, const void* g) {
    asm volatile("cp.async.ca.shared.global [%0], [%1], 16;" :: "r"(saddr), "l"(g));
}
__device__ __forceinline__ float b2f(u16 v) {
    return __bfloat162float(__ushort_as_bfloat16(v));
}
__device__ __forceinline__ void ldmx4t(u32* r, u32 saddr) {
    asm volatile(
        "ldmatrix.sync.aligned.m8n8.x4.trans.shared.b16 {%0,%1,%2,%3}, [%4];"
        : "=r"(r[0]), "=r"(r[1]), "=r"(r[2]), "=r"(r[3]) : "r"(saddr));
}

// ---------------- 2-stage cp.async bf16 hi/lo GEMM --------------------------
// GSYM=1: symmetric G schedule (triangle tiles x split-K 3, diag aliases B=A).
// BLAYOUT=0: B rows = N-dim [n][k] (xt-style). BLAYOUT=1: B in y layout
//   [k][n] rows; fragments via ldmatrix.trans; pitch 136 u16.
// EPI 0: fp32 C at zout*sC. EPI 1: out = D + cv + x (residual from B tile).
template <int EPI, int GSYM, int BLAYOUT>
__global__ void __launch_bounds__(256, 1) bgemm(
    const bf16* __restrict__ Ahg, const bf16* __restrict__ Alg,
    const bf16* __restrict__ Bhg, const bf16* __restrict__ Blg,
    float* __restrict__ C, int T, int lda, int ldb, long sA, long sB, long sC,
    int bmask, int sb, int kps,
    const float* __restrict__ cvv, float* __restrict__ outp)
{
    constexpr int BPITCH = BLAYOUT ? 136 : 40;
    constexpr int BSIZE  = BLAYOUT ? 32 * 136 : 128 * 40;  // u16 per B tile
    constexpr int BOFF   = 10240;                          // after Ah+Al
    constexpr int STGU   = BOFF + 2 * BSIZE;               // u16 per stage

    extern __shared__ __align__(16) u16 smp[];
    int tid = threadIdx.x, lane = tid & 31, wid = tid >> 5;
    int wm = wid >> 2, wn = wid & 3;
    int bx, by, b, kbase, Titer, zout;
    if (GSYM) {
        int t = blockIdx.x;
        by = (t + 1) >> 1; bx = t >> 1;          // {0:(0,0),1:(1,0),2:(1,1)}
        int kc = blockIdx.y;
        b = blockIdx.z;
        kbase = kc * 1376;                       // 43 iters * 32
        Titer = (kc == 2) ? 42 : 43;
        zout = kc * 16 + b;
    } else {
        bx = blockIdx.x; by = blockIdx.y;
        int z = blockIdx.z;
        b = z & bmask;
        kbase = (z >> sb) * kps;
        Titer = T;
        zout = z;
    }
    bool diag = GSYM && (bx == by);

    const bf16* Abh = Ahg + (size_t)b * sA + (size_t)(by * 128) * lda + kbase;
    const bf16* Abl = Alg + (size_t)b * sA + (size_t)(by * 128) * lda + kbase;
    const bf16 *Bbh, *Bbl;
    if (BLAYOUT) {
        Bbh = Bhg + (size_t)b * sB + bx * 128;
        Bbl = Blg + (size_t)b * sB + bx * 128;
    } else {
        Bbh = Bhg + (size_t)b * sB + (size_t)(bx * 128) * ldb + kbase;
        Bbl = Blg + (size_t)b * sB + (size_t)(bx * 128) * ldb + kbase;
    }

    u32 sbase;
    asm("{ .reg .u64 t; cvta.to.shared.u64 t, %1; cvt.u32.u64 %0, t; }"
        : "=r"(sbase) : "l"(smp));

    auto PREF = [&](int t) {
        if (t < Titer) {
            int k0 = t * 32, st = t & 1;
            u32 s0 = sbase + (u32)(st * STGU) * 2;
#pragma unroll
            for (int j = 0; j < 2; j++) {
                int idx = tid * 2 + j;          // 0..511
                int rA = idx >> 2, cA8 = (idx & 3) * 8;
                u32 offA = (u32)(rA * 40 + cA8) * 2;
                cp16(s0 + offA,         Abh + (size_t)rA * lda + k0 + cA8);
                cp16(s0 + offA + 10240, Abl + (size_t)rA * lda + k0 + cA8);
                if (BLAYOUT) {
                    int rB = idx >> 4, cB8 = (idx & 15) * 8;
                    u32 offB = (u32)(BOFF + rB * 136 + cB8) * 2;
                    cp16(s0 + offB, Bbh + (size_t)(k0 + rB) * ldb + cB8);
                    cp16(s0 + offB + (u32)BSIZE * 2, Bbl + (size_t)(k0 + rB) * ldb + cB8);
                } else if (!diag) {
                    u32 offB = (u32)(BOFF + idx * 40 / 4 * 0) * 0; (void)offB;
                    u32 ob = (u32)(BOFF) * 2 + (u32)(rA * 40 + cA8) * 2;
                    cp16(s0 + ob, Bbh + (size_t)rA * ldb + k0 + cA8);
                    cp16(s0 + ob + (u32)BSIZE * 2, Bbl + (size_t)rA * ldb + k0 + cA8);
                }
            }
        }
        asm volatile("cp.async.commit_group;" ::: "memory");
    };

    float acc[4][4][4] = {};
    PREF(0);
    for (int t = 0; t < Titer; t++) {
        PREF(t + 1);
        asm volatile("cp.async.wait_group 1;" ::: "memory");
        __syncthreads();
        int st = t & 1;
        u16 (*Ah)[40] = (u16(*)[40])(smp + st * STGU);
        u16 (*Al)[40] = (u16(*)[40])(smp + st * STGU + 5120);
        u16 (*BhT)[BPITCH] = (u16(*)[BPITCH])(smp + st * STGU + BOFF);
        u16 (*BlT)[BPITCH] = (u16(*)[BPITCH])(smp + st * STGU + BOFF + BSIZE);
        u16 (*Bh)[40] = diag ? Ah : (u16(*)[40])BhT;
        u16 (*Bl)[40] = diag ? Al : (u16(*)[40])BlT;
#pragma unroll
        for (int kc = 0; kc < 32; kc += 16) {
            int kk = kc + (lane & 3) * 2;
            u32 afh[4][4], afl[4][4], bfh[4][2], bfl[4][2];
#pragma unroll
            for (int mf = 0; mf < 4; mf++) {
                int r0 = wm * 64 + mf * 16 + (lane >> 2);
                afh[mf][0] = *(const u32*)&Ah[r0][kk];
                afh[mf][1] = *(const u32*)&Ah[r0 + 8][kk];
                afh[mf][2] = *(const u32*)&Ah[r0][kk + 8];
                afh[mf][3] = *(const u32*)&Ah[r0 + 8][kk + 8];
                afl[mf][0] = *(const u32*)&Al[r0][kk];
                afl[mf][1] = *(const u32*)&Al[r0 + 8][kk];
                afl[mf][2] = *(const u32*)&Al[r0][kk + 8];
                afl[mf][3] = *(const u32*)&Al[r0 + 8][kk + 8];
            }
            if (BLAYOUT) {
                // B fragments via ldmatrix.trans from [k][n] layout
                int jj = lane >> 3;
                int rrow = kc + (jj & 1) * 8 + (lane & 7);
                u32 base = sbase + (u32)(st * STGU + BOFF + rrow * 136) * 2;
                u32 a0 = base + (u32)(wn * 32 + (jj >> 1) * 8) * 2;
                u32 a1 = a0 + 32;  // +16 cols
                u32 rb[8], rbl2[8];
                ldmx4t(rb + 0, a0);
                ldmx4t(rb + 4, a1);
                ldmx4t(rbl2 + 0, a0 + (u32)BSIZE * 2);
                ldmx4t(rbl2 + 4, a1 + (u32)BSIZE * 2);
#pragma unroll
                for (int nf = 0; nf < 4; nf++) {
                    bfh[nf][0] = rb[nf * 2];
                    bfh[nf][1] = rb[nf * 2 + 1];
                    bfl[nf][0] = rbl2[nf * 2];
                    bfl[nf][1] = rbl2[nf * 2 + 1];
                }
            } else {
#pragma unroll
                for (int nf = 0; nf < 4; nf++) {
                    int c0 = wn * 32 + nf * 8 + (lane >> 2);
                    bfh[nf][0] = *(const u32*)&Bh[c0][kk];
                    bfh[nf][1] = *(const u32*)&Bh[c0][kk + 8];
                    bfl[nf][0] = *(const u32*)&Bl[c0][kk];
                    bfl[nf][1] = *(const u32*)&Bl[c0][kk + 8];
                }
            }
#pragma unroll
            for (int mf = 0; mf < 4; mf++)
#pragma unroll
                for (int nf = 0; nf < 4; nf++) {
                    mma16816(acc[mf][nf], afh[mf], bfh[nf]);
                    mma16816(acc[mf][nf], afh[mf], bfl[nf]);
                    mma16816(acc[mf][nf], afl[mf], bfh[nf]);
                }
        }
        if (EPI == 1 && BLAYOUT) {
            // residual x[rg][cg]: B tile holds y[d=32t..32t+32][n]; present when
            // t == rg>>5. Row in tile = (mf&1)*16 + lane/4, cols direct.
            int tb = by * 4 + wm * 2;
#pragma unroll
            for (int mf = 0; mf < 4; mf++) {
                if (t == tb + (mf >> 1)) {
                    int row = (mf & 1) * 16 + (lane >> 2);
#pragma unroll
                    for (int nf = 0; nf < 4; nf++) {
                        int cl = wn * 32 + nf * 8 + (lane & 3) * 2;
                        acc[mf][nf][0] += b2f(BhT[row][cl]) + b2f(BlT[row][cl]);
                        acc[mf][nf][1] += b2f(BhT[row][cl + 1]) + b2f(BlT[row][cl + 1]);
                        acc[mf][nf][2] += b2f(BhT[row + 8][cl]) + b2f(BlT[row + 8][cl]);
                        acc[mf][nf][3] += b2f(BhT[row + 8][cl + 1]) + b2f(BlT[row + 8][cl + 1]);
                    }
                }
            }
        }
        __syncthreads();
    }

#pragma unroll
    for (int mf = 0; mf < 4; mf++) {
        int rg = by * 128 + wm * 64 + mf * 16 + (lane >> 2);
#pragma unroll
        for (int nf = 0; nf < 4; nf++) {
            int cg = bx * 128 + wn * 32 + nf * 8 + (lane & 3) * 2;
            float* a = acc[mf][nf];
            if (EPI == 0) {
                float* p = C + (size_t)zout * sC + (size_t)rg * CC + cg;
                *(float2*)p = make_float2(a[0], a[1]);
                *(float2*)(p + 8 * CC) = make_float2(a[2], a[3]);
            } else {
                size_t o0 = (size_t)b * CC * NPIX + (size_t)rg * NPIX + cg;
                size_t o1 = o0 + 8 * NPIX;
                float cv0 = cvv[b * CC + rg];
                float cv1 = cvv[b * CC + rg + 8];
                *(float2*)(outp + o0) = make_float2(a[0] + cv0, a[1] + cv0);
                *(float2*)(outp + o1) = make_float2(a[2] + cv1, a[3] + cv1);
            }
        }
    }
}

// ---------------- fp32-input hi/lo mma GEMM (small GEMMs; proven) -----------
// EPI 0: fp32 C. EPI 1: write bf16 hi/lo pair into g_Mh/g_Ml (splitm folded).
template <int EPI>
__global__ void __launch_bounds__(256, 1) mgemm(
    const float* __restrict__ A, const float* __restrict__ B, float* __restrict__ C,
    int K, int lda, int ldb, long sA, long sB, long sC)
{
    __shared__ __align__(16) u16 Ah[128][40], Al[128][40];
    __shared__ __align__(16) u16 Bh[128][40], Bl[128][40];
    int tid = threadIdx.x, lane = tid & 31, wid = tid >> 5;
    int wm = wid >> 2, wn = wid & 3;
    int bx = blockIdx.x, by = blockIdx.y, b = blockIdx.z;
    const float* Ab = A + (size_t)b * sA + (size_t)(by * 128) * lda;
    const float* Bb = B + (size_t)b * sB;
    float acc[4][4][4] = {};
    float4 va[4], vb[4];
    int arow = tid >> 1, acb = (tid & 1) * 16;
    auto LDG = [&](int k0) {
#pragma unroll
        for (int j = 0; j < 4; j++) {
            va[j] = *(const float4*)(Ab + (size_t)arow * lda + k0 + acb + 4 * j);
            vb[j] = *(const float4*)(Bb + (size_t)(bx * 128 + arow) * ldb + k0 + acb + 4 * j);
        }
    };
    auto STS = [&]() {
#pragma unroll
        for (int j = 0; j < 4; j++) {
            uint2 h, l;
            cvt4(va[j], h, l);
            *(uint2*)&Ah[arow][acb + 4 * j] = h;
            *(uint2*)&Al[arow][acb + 4 * j] = l;
            cvt4(vb[j], h, l);
            *(uint2*)&Bh[arow][acb + 4 * j] = h;
            *(uint2*)&Bl[arow][acb + 4 * j] = l;
        }
    };
    int T = K >> 5;
    LDG(0);
    for (int t = 0; t < T; t++) {
        STS();
        __syncthreads();
        if (t + 1 < T) LDG((t + 1) << 5);
#pragma unroll
        for (int kc = 0; kc < 32; kc += 16) {
            int kk = kc + (lane & 3) * 2;
            u32 afh[4][4], afl[4][4], bfh[4][2], bfl[4][2];
#pragma unroll
            for (int mf = 0; mf < 4; mf++) {
                int r0 = wm * 64 + mf * 16 + (lane >> 2);
                afh[mf][0] = *(const u32*)&Ah[r0][kk];
                afh[mf][1] = *(const u32*)&Ah[r0 + 8][kk];
                afh[mf][2] = *(const u32*)&Ah[r0][kk + 8];
                afh[mf][3] = *(const u32*)&Ah[r0 + 8][kk + 8];
                afl[mf][0] = *(const u32*)&Al[r0][kk];
                afl[mf][1] = *(const u32*)&Al[r0 + 8][kk];
                afl[mf][2] = *(const u32*)&Al[r0][kk + 8];
                afl[mf][3] = *(const u32*)&Al[r0 + 8][kk + 8];
            }
#pragma unroll
            for (int nf = 0; nf < 4; nf++) {
                int c0 = wn * 32 + nf * 8 + (lane >> 2);
                bfh[nf][0] = *(const u32*)&Bh[c0][kk];
                bfh[nf][1] = *(const u32*)&Bh[c0][kk + 8];
                bfl[nf][0] = *(const u32*)&Bl[c0][kk];
                bfl[nf][1] = *(const u32*)&Bl[c0][kk + 8];
            }
#pragma unroll
            for (int mf = 0; mf < 4; mf++)
#pragma unroll
                for (int nf = 0; nf < 4; nf++) {
                    mma16816(acc[mf][nf], afh[mf], bfh[nf]);
                    mma16816(acc[mf][nf], afh[mf], bfl[nf]);
                    mma16816(acc[mf][nf], afl[mf], bfh[nf]);
                }
        }
        __syncthreads();
    }
#pragma unroll
    for (int mf = 0; mf < 4; mf++) {
        int rg = by * 128 + wm * 64 + mf * 16 + (lane >> 2);
#pragma unroll
        for (int nf = 0; nf < 4; nf++) {
            int cg = bx * 128 + wn * 32 + nf * 8 + (lane & 3) * 2;
            float* a = acc[mf][nf];
            if (EPI == 0) {
                float* p = C + (size_t)b * sC + (size_t)rg * CC + cg;
                *(float2*)p = make_float2(a[0], a[1]);
                *(float2*)(p + 8 * CC) = make_float2(a[2], a[3]);
            } else {
                size_t i0 = (size_t)b * CC * CC + (size_t)rg * CC + cg;
                size_t i1 = i0 + 8 * CC;
                bf16 h0, l0, h1, l1;
                split2(a[0], h0, l0); split2(a[1], h1, l1);
                *(u32*)&g_Mh[i0] = pack2(h0, h1);
                *(u32*)&g_Ml[i0] = pack2(l0, l1);
                split2(a[2], h0, l0); split2(a[3], h1, l1);
                *(u32*)&g_Mh[i1] = pack2(h0, h1);
                *(u32*)&g_Ml[i1] = pack2(l0, l1);
            }
        }
    }
}

// ---------------- split x -> yh/yl and row-sum partials ---------------------
__global__ void splitx_kernel(const float* __restrict__ x) {
    int b = blockIdx.z, c0 = blockIdx.y * 32, n0 = blockIdx.x * 32;
    int tid = threadIdx.x;
    int c = tid >> 3, n4 = (tid & 7) * 4;
    float4 v = *(const float4*)(x + ((size_t)(b * CC + c0 + c)) * NPIX + n0 + n4);
    bf16 h[4], l[4];
    split2(v.x, h[0], l[0]); split2(v.y, h[1], l[1]);
    split2(v.z, h[2], l[2]); split2(v.w, h[3], l[3]);
    size_t yo = ((size_t)(b * CC + c0 + c)) * NPIX + n0 + n4;
    *(uint2*)(g_yh + yo) = make_uint2(pack2(h[0], h[1]), pack2(h[2], h[3]));
    *(uint2*)(g_yl + yo) = make_uint2(pack2(l[0], l[1]), pack2(l[2], l[3]));
    float ps = (v.x + v.y) + (v.z + v.w);
#pragma unroll
    for (int o = 4; o; o >>= 1) ps += __shfl_down_sync(0xFFFFFFFFu, ps, o, 8);
    if ((tid & 7) == 0)
        g_sxp[(size_t)(b * CC + c0 + c) * 128 + blockIdx.x] = ps;
}

// ---------------- reduce row-sum partials: warp per row ---------------------
__global__ void reduce_sx_kernel() {
    int row = blockIdx.x * 8 + (threadIdx.x >> 5);
    int lane = threadIdx.x & 31;
    const float* p = g_sxp + (size_t)row * 128;
    float s = 0.f;
#pragma unroll
    for (int j = 0; j < 4; j++) s += p[lane + 32 * j];
#pragma unroll
    for (int o = 16; o; o >>= 1) s += __shfl_down_sync(0xFFFFFFFFu, s, o);
    if (lane == 0) g_sx[row] = s;
}

// ---------------- qs/ks: warp per output, grid-parallel ---------------------
__global__ void proj_sums(const float* __restrict__ wq, const float* __restrict__ wk) {
    __shared__ float sxs[CC];
    int b = blockIdx.x, mat = blockIdx.y, zc = blockIdx.z;
    int tid = threadIdx.x, lane = tid & 31, wid = tid >> 5;
    sxs[tid] = g_sx[b * CC + tid];
    __syncthreads();
    const float* w = mat ? wk : wq;
    float* outv = mat ? g_ks : g_qs;
#pragma unroll
    for (int i = 0; i < 4; i++) {
        int o = zc * 32 + wid * 4 + i;
        const float* r = w + o * CC;
        float s = 0.f;
#pragma unroll
        for (int j = 0; j < 8; j++) {
            int cidx = lane + 32 * j;
            s += r[cidx] * sxs[cidx];
        }
#pragma unroll
        for (int off = 16; off; off >>= 1) s += __shfl_down_sync(0xFFFFFFFFu, s, off);
        if (lane == 0) outv[b * CC + o] = s;
    }
}

// ---------------- softmax (+ folded cv = A bv) ------------------------------
__global__ void softmax_kernel(const float* __restrict__ bq, const float* __restrict__ bk,
                               const float* __restrict__ bv) {
    int row = blockIdx.x;
    int b = row >> 8, c = row & 255;
    int d = threadIdx.x;
    __shared__ float red[256];
    float v = g_L[(size_t)row * CC + d];
    float bqc = bq[c];
    v += g_qs[b * CC + c] * bk[d] + bqc * g_ks[b * CC + d] + 4096.f * bqc * bk[d];
    v *= 0.0625f;
    red[d] = v;
    __syncthreads();
#pragma unroll
    for (int s = 128; s; s >>= 1) { if (d < s) red[d] = fmaxf(red[d], red[d + s]); __syncthreads(); }
    float m = red[0];
    __syncthreads();
    float e = __expf(v - m);
    red[d] = e;
    __syncthreads();
#pragma unroll
    for (int s = 128; s; s >>= 1) { if (d < s) red[d] += red[d + s]; __syncthreads(); }
    float p = e * (1.0f / red[0]);
    g_L[(size_t)row * CC + d] = p;
    __syncthreads();
    red[d] = p * bv[d];
    __syncthreads();
#pragma unroll
    for (int s = 128; s; s >>= 1) { if (d < s) red[d] += red[d + s]; __syncthreads(); }
    if (d == 0) g_cv[row] = red[0];
}

// ---------------- misc small kernels ----------------------------------------
__global__ void wvt_kernel(const float* __restrict__ wv) {
    int d = blockIdx.x, e = threadIdx.x;
    g_Wvt[e * CC + d] = wv[d * CC + e];
}
__global__ void reduceg_kernel() {
    int i = (blockIdx.x * 256 + threadIdx.x) * 4;
    float4 a = *(const float4*)(g_Gp + i);
    float4 b = *(const float4*)(g_Gp + (size_t)BB * CC * CC + i);
    float4 c = *(const float4*)(g_Gp + (size_t)2 * BB * CC * CC + i);
    *(float4*)(g_G + i) = make_float4(a.x + b.x + c.x, a.y + b.y + c.y,
                                      a.z + b.z + c.z, a.w + b.w + c.w);
}
// mirror: G[b][c][128+j] = G[b][128+j][c]  (fills the skipped (0,1) tile)
__global__ void mirror_kernel() {
    __shared__ float s[32][33];
    int b = blockIdx.z;
    int r0 = 128 + blockIdx.y * 32;
    int c0 = blockIdx.x * 32;
    float* Gb = g_G + (size_t)b * CC * CC;
    int tx = threadIdx.x & 31, ty = threadIdx.x >> 5;
#pragma unroll
    for (int i = ty; i < 32; i += 8)
        s[i][tx] = Gb[(size_t)(r0 + i) * CC + c0 + tx];
    __syncthreads();
#pragma unroll
    for (int i = ty; i < 32; i += 8)
        Gb[(size_t)(c0 + i) * CC + r0 + tx] = s[tx][i];
}

// ---------------- launcher ----------------
extern "C" void kernel_launch(void* const* d_in, const int* in_sizes, int n_in,
                              void* d_out, int out_size) {
    const float* x  = (const float*)d_in[0];
    const float* wq = (const float*)d_in[1];
    const float* bq = (const float*)d_in[2];
    const float* wk = (const float*)d_in[3];
    const float* bk = (const float*)d_in[4];
    const float* wv = (const float*)d_in[5];
    const float* bv = (const float*)d_in[6];
    float* out = (float*)d_out;

    float *pG, *pGp, *pT, *pL, *pWvt, *pcv;
    bf16 *pyh, *pyl, *pMh, *pMl;
    cudaGetSymbolAddress((void**)&pG, g_G);
    cudaGetSymbolAddress((void**)&pGp, g_Gp);
    cudaGetSymbolAddress((void**)&pT, g_T);
    cudaGetSymbolAddress((void**)&pL, g_L);
    cudaGetSymbolAddress((void**)&pWvt, g_Wvt);
    cudaGetSymbolAddress((void**)&pcv, g_cv);
    cudaGetSymbolAddress((void**)&pyh, g_yh);
    cudaGetSymbolAddress((void**)&pyl, g_yl);
    cudaGetSymbolAddress((void**)&pMh, g_Mh);
    cudaGetSymbolAddress((void**)&pMl, g_Ml);

    const int SMEMB0 = 2 * 20480 * 2;   // G path: 81920 B
    const int SMEMB1 = 2 * 18944 * 2;   // stage C path: 75776 B
    cudaFuncSetAttribute((const void*)bgemm<0, 1, 0>, cudaFuncAttributeMaxDynamicSharedMemorySize, SMEMB0);
    cudaFuncSetAttribute((const void*)bgemm<1, 0, 1>, cudaFuncAttributeMaxDynamicSharedMemorySize, SMEMB1);

    const long CN = (long)CC * NPIX;
    const long C2 = (long)CC * CC;

    splitx_kernel<<<dim3(128, 8, 16), 256>>>(x);
    reduce_sx_kernel<<<512, 256>>>();
    wvt_kernel<<<256, 256>>>(wv);
    proj_sums<<<dim3(16, 2, 8), 256>>>(wq, wk);
    // G partials: y y^T bf16, symmetric triangle tiles x split-K 3
    bgemm<0, 1, 0><<<dim3(3, 3, 16), 256, SMEMB0>>>(pyh, pyl, pyh, pyl, pGp,
                                                    0, NPIX, NPIX, CN, CN, C2, 0, 0, 0,
                                                    nullptr, nullptr);
    reduceg_kernel<<<1024, 256>>>();
    mirror_kernel<<<dim3(4, 4, 16), 256>>>();
    // T = Wq G ; L = T Wk^T ; softmax(+cv) ; M = A Wv^T (bf16 epilogue)
    mgemm<0><<<dim3(2, 2, 16), 256>>>(wq, pG, pT, CC, CC, CC, 0, C2, C2);
    mgemm<0><<<dim3(2, 2, 16), 256>>>(pT, wk, pL, CC, CC, CC, C2, 0, C2);
    softmax_kernel<<<4096, 256>>>(bq, bk, bv);
    mgemm<1><<<dim3(2, 2, 16), 256>>>(pL, pWvt, nullptr, CC, CC, CC, C2, 0, 0);
    // out = x + M x + cv  (A = M hi/lo [c][d], B = y hi/lo [d][n], T = 8)
    bgemm<1, 0, 1><<<dim3(32, 2, 16), 256, SMEMB1>>>(pMh, pMl, pyh, pyl, nullptr,
                                                     8, CC, NPIX, C2, CN, 0, 255, 8, 0,
                                                     pcv, out);
}

// round 14
// speedup vs baseline: 2.6649x; 1.0604x over previous
#include <cuda_runtime.h>
#include <cuda_bf16.h>

#define BB 16
#define CC 256
#define NPIX 4096
typedef __nv_bfloat16 bf16;
typedef unsigned int u32;
typedef unsigned short u16;

// ---------------- scratch (device globals) ----------------
__device__ float g_G[BB * CC * CC];
__device__ float g_Gp[3 * BB * CC * CC];
__device__ float g_T[BB * CC * CC];
__device__ float g_L[BB * CC * CC];
__device__ float g_Wvt[CC * CC];
__device__ float g_sxp[BB * CC * 128];
__device__ float g_sx[BB * CC], g_qs[BB * CC], g_ks[BB * CC], g_cv[BB * CC];
__device__ __align__(16) bf16 g_yh[(size_t)BB * CC * NPIX];
__device__ __align__(16) bf16 g_yl[(size_t)BB * CC * NPIX];
__device__ __align__(16) bf16 g_Mh[BB * CC * CC];
__device__ __align__(16) bf16 g_Ml[BB * CC * CC];

// ---------------- helpers ----------------
__device__ __forceinline__ void split2(float f, bf16& h, bf16& l) {
    h = __float2bfloat16(f);
    l = __float2bfloat16(f - __bfloat162float(h));
}
__device__ __forceinline__ u32 pack2(bf16 a, bf16 b) {
    return (u32)__bfloat16_as_ushort(a) | ((u32)__bfloat16_as_ushort(b) << 16);
}
__device__ __forceinline__ void cvt4(float4 v, uint2& h, uint2& l) {
    bf16 h0, l0, h1, l1, h2, l2, h3, l3;
    split2(v.x, h0, l0); split2(v.y, h1, l1);
    split2(v.z, h2, l2); split2(v.w, h3, l3);
    h = make_uint2(pack2(h0, h1), pack2(h2, h3));
    l = make_uint2(pack2(l0, l1), pack2(l2, l3));
}
__device__ __forceinline__ void mma16816(float* c, const u32* a, const u32* b) {
    asm volatile(
        "mma.sync.aligned.m16n8k16.row.col.f32.bf16.bf16.f32 "
        "{%0,%1,%2,%3}, {%4,%5,%6,%7}, {%8,%9}, {%0,%1,%2,%3};"
        : "+f"(c[0]), "+f"(c[1]), "+f"(c[2]), "+f"(c[3])
        : "r"(a[0]), "r"(a[1]), "r"(a[2]), "r"(a[3]), "r"(b[0]), "r"(b[1]));
}
__device__ __forceinline__ void cp16(u32 saddr, const void* g) {
    asm volatile("cp.async.ca.shared.global [%0], [%1], 16;" :: "r"(saddr), "l"(g));
}
__device__ __forceinline__ float b2f(u16 v) {
    return __bfloat162float(__ushort_as_bfloat16(v));
}
__device__ __forceinline__ void ldmx4t(u32* r, u32 saddr) {
    asm volatile(
        "ldmatrix.sync.aligned.m8n8.x4.trans.shared.b16 {%0,%1,%2,%3}, [%4];"
        : "=r"(r[0]), "=r"(r[1]), "=r"(r[2]), "=r"(r[3]) : "r"(saddr));
}
__device__ __forceinline__ void ldmx4(u32* r, u32 saddr) {
    asm volatile(
        "ldmatrix.sync.aligned.m8n8.x4.shared.b16 {%0,%1,%2,%3}, [%4];"
        : "=r"(r[0]), "=r"(r[1]), "=r"(r[2]), "=r"(r[3]) : "r"(saddr));
}

// ---------------- 2-stage cp.async bf16 hi/lo GEMM --------------------------
// GSYM=1: symmetric G schedule (triangle tiles x split-K 3, diag aliases B=A).
// BLAYOUT=0: B rows = N-dim [n][k]. BLAYOUT=1: B in y layout [k][n] rows;
//   fragments via ldmatrix.trans; pitch 136 u16.
// All fragments loaded via ldmatrix.x4.
// EPI 0: fp32 C at zout*sC. EPI 1: out = D + cv + x (residual from B tile).
template <int EPI, int GSYM, int BLAYOUT>
__global__ void __launch_bounds__(256, 1) bgemm(
    const bf16* __restrict__ Ahg, const bf16* __restrict__ Alg,
    const bf16* __restrict__ Bhg, const bf16* __restrict__ Blg,
    float* __restrict__ C, int T, int lda, int ldb, long sA, long sB, long sC,
    int bmask, int sb, int kps,
    const float* __restrict__ cvv, float* __restrict__ outp)
{
    constexpr int BPITCH = BLAYOUT ? 136 : 40;
    constexpr int BSIZE  = BLAYOUT ? 32 * 136 : 128 * 40;  // u16 per B tile
    constexpr int BOFF   = 10240;                          // after Ah+Al
    constexpr int STGU   = BOFF + 2 * BSIZE;               // u16 per stage

    extern __shared__ __align__(16) u16 smp[];
    int tid = threadIdx.x, lane = tid & 31, wid = tid >> 5;
    int wm = wid >> 2, wn = wid & 3;
    int bx, by, b, kbase, Titer, zout;
    if (GSYM) {
        int t = blockIdx.x;
        by = (t + 1) >> 1; bx = t >> 1;          // {0:(0,0),1:(1,0),2:(1,1)}
        int kc = blockIdx.y;
        b = blockIdx.z;
        kbase = kc * 1376;                       // 43 iters * 32
        Titer = (kc == 2) ? 42 : 43;
        zout = kc * 16 + b;
    } else {
        bx = blockIdx.x; by = blockIdx.y;
        int z = blockIdx.z;
        b = z & bmask;
        kbase = (z >> sb) * kps;
        Titer = T;
        zout = z;
    }
    bool diag = GSYM && (bx == by);

    const bf16* Abh = Ahg + (size_t)b * sA + (size_t)(by * 128) * lda + kbase;
    const bf16* Abl = Alg + (size_t)b * sA + (size_t)(by * 128) * lda + kbase;
    const bf16 *Bbh, *Bbl;
    if (BLAYOUT) {
        Bbh = Bhg + (size_t)b * sB + bx * 128;
        Bbl = Blg + (size_t)b * sB + bx * 128;
    } else {
        Bbh = Bhg + (size_t)b * sB + (size_t)(bx * 128) * ldb + kbase;
        Bbl = Blg + (size_t)b * sB + (size_t)(bx * 128) * ldb + kbase;
    }

    u32 sbase;
    asm("{ .reg .u64 t; cvta.to.shared.u64 t, %1; cvt.u32.u64 %0, t; }"
        : "=r"(sbase) : "l"(smp));

    auto PREF = [&](int t) {
        if (t < Titer) {
            int k0 = t * 32, st = t & 1;
            u32 s0 = sbase + (u32)(st * STGU) * 2;
#pragma unroll
            for (int j = 0; j < 2; j++) {
                int idx = tid * 2 + j;          // 0..511
                int rA = idx >> 2, cA8 = (idx & 3) * 8;
                u32 offA = (u32)(rA * 40 + cA8) * 2;
                cp16(s0 + offA,         Abh + (size_t)rA * lda + k0 + cA8);
                cp16(s0 + offA + 10240, Abl + (size_t)rA * lda + k0 + cA8);
                if (BLAYOUT) {
                    int rB = idx >> 4, cB8 = (idx & 15) * 8;
                    u32 offB = (u32)(BOFF + rB * 136 + cB8) * 2;
                    cp16(s0 + offB, Bbh + (size_t)(k0 + rB) * ldb + cB8);
                    cp16(s0 + offB + (u32)BSIZE * 2, Bbl + (size_t)(k0 + rB) * ldb + cB8);
                } else if (!diag) {
                    u32 ob = (u32)BOFF * 2 + offA;
                    cp16(s0 + ob, Bbh + (size_t)rA * ldb + k0 + cA8);
                    cp16(s0 + ob + (u32)BSIZE * 2, Bbl + (size_t)rA * ldb + k0 + cA8);
                }
            }
        }
        asm volatile("cp.async.commit_group;" ::: "memory");
    };

    float acc[4][4][4] = {};
    PREF(0);
    for (int t = 0; t < Titer; t++) {
        PREF(t + 1);
        asm volatile("cp.async.wait_group 1;" ::: "memory");
        __syncthreads();
        int st = t & 1;
        u16 (*BhT)[BPITCH] = (u16(*)[BPITCH])(smp + st * STGU + BOFF);
        u16 (*BlT)[BPITCH] = (u16(*)[BPITCH])(smp + st * STGU + BOFF + BSIZE);
        u32 stg2 = sbase + (u32)(st * STGU) * 2;
        int lrow = lane & 7, lm = lane >> 3;
#pragma unroll
        for (int kc = 0; kc < 32; kc += 16) {
            u32 afh[4][4], afl[4][4], bfh[4][2], bfl[4][2];
            // A fragments: one ldmatrix.x4 per mf per array
#pragma unroll
            for (int mf = 0; mf < 4; mf++) {
                int r = wm * 64 + mf * 16 + ((lm & 1) << 3) + lrow;
                int cc2 = kc + ((lm & 2) << 2);
                u32 addr = stg2 + (u32)(r * 40 + cc2) * 2;
                ldmx4(afh[mf], addr);
                ldmx4(afl[mf], addr + 10240);
            }
            if (BLAYOUT) {
                int jj = lane >> 3;
                int rrow = kc + (jj & 1) * 8 + (lane & 7);
                u32 base = sbase + (u32)(st * STGU + BOFF + rrow * 136) * 2;
                u32 a0 = base + (u32)(wn * 32 + (jj >> 1) * 8) * 2;
                u32 a1 = a0 + 32;
                u32 rb[8], rbl2[8];
                ldmx4t(rb + 0, a0);
                ldmx4t(rb + 4, a1);
                ldmx4t(rbl2 + 0, a0 + (u32)BSIZE * 2);
                ldmx4t(rbl2 + 4, a1 + (u32)BSIZE * 2);
#pragma unroll
                for (int nf = 0; nf < 4; nf++) {
                    bfh[nf][0] = rb[nf * 2];
                    bfh[nf][1] = rb[nf * 2 + 1];
                    bfl[nf][0] = rbl2[nf * 2];
                    bfl[nf][1] = rbl2[nf * 2 + 1];
                }
            } else {
                u32 bofs = diag ? 0u : (u32)BOFF * 2;
                u32 dlo  = diag ? 10240u : (u32)BSIZE * 2;
#pragma unroll
                for (int np = 0; np < 2; np++) {
                    int r = wn * 32 + np * 16 + ((lm & 2) << 2) + lrow;
                    int cc2 = kc + ((lm & 1) << 3);
                    u32 addr = stg2 + bofs + (u32)(r * 40 + cc2) * 2;
                    u32 rr[4];
                    ldmx4(rr, addr);
                    bfh[np * 2][0] = rr[0]; bfh[np * 2][1] = rr[1];
                    bfh[np * 2 + 1][0] = rr[2]; bfh[np * 2 + 1][1] = rr[3];
                    ldmx4(rr, addr + dlo);
                    bfl[np * 2][0] = rr[0]; bfl[np * 2][1] = rr[1];
                    bfl[np * 2 + 1][0] = rr[2]; bfl[np * 2 + 1][1] = rr[3];
                }
            }
#pragma unroll
            for (int mf = 0; mf < 4; mf++)
#pragma unroll
                for (int nf = 0; nf < 4; nf++) {
                    mma16816(acc[mf][nf], afh[mf], bfh[nf]);
                    mma16816(acc[mf][nf], afh[mf], bfl[nf]);
                    mma16816(acc[mf][nf], afl[mf], bfh[nf]);
                }
        }
        if (EPI == 1 && BLAYOUT) {
            int tb = by * 4 + wm * 2;
#pragma unroll
            for (int mf = 0; mf < 4; mf++) {
                if (t == tb + (mf >> 1)) {
                    int row = (mf & 1) * 16 + (lane >> 2);
#pragma unroll
                    for (int nf = 0; nf < 4; nf++) {
                        int cl = wn * 32 + nf * 8 + (lane & 3) * 2;
                        acc[mf][nf][0] += b2f(BhT[row][cl]) + b2f(BlT[row][cl]);
                        acc[mf][nf][1] += b2f(BhT[row][cl + 1]) + b2f(BlT[row][cl + 1]);
                        acc[mf][nf][2] += b2f(BhT[row + 8][cl]) + b2f(BlT[row + 8][cl]);
                        acc[mf][nf][3] += b2f(BhT[row + 8][cl + 1]) + b2f(BlT[row + 8][cl + 1]);
                    }
                }
            }
        }
        __syncthreads();
    }

#pragma unroll
    for (int mf = 0; mf < 4; mf++) {
        int rg = by * 128 + wm * 64 + mf * 16 + (lane >> 2);
#pragma unroll
        for (int nf = 0; nf < 4; nf++) {
            int cg = bx * 128 + wn * 32 + nf * 8 + (lane & 3) * 2;
            float* a = acc[mf][nf];
            if (EPI == 0) {
                float* p = C + (size_t)zout * sC + (size_t)rg * CC + cg;
                *(float2*)p = make_float2(a[0], a[1]);
                *(float2*)(p + 8 * CC) = make_float2(a[2], a[3]);
            } else {
                size_t o0 = (size_t)b * CC * NPIX + (size_t)rg * NPIX + cg;
                size_t o1 = o0 + 8 * NPIX;
                float cv0 = cvv[b * CC + rg];
                float cv1 = cvv[b * CC + rg + 8];
                *(float2*)(outp + o0) = make_float2(a[0] + cv0, a[1] + cv0);
                *(float2*)(outp + o1) = make_float2(a[2] + cv1, a[3] + cv1);
            }
        }
    }
}

// ---------------- fp32-input hi/lo mma GEMM (small GEMMs; proven) -----------
// EPI 0: fp32 C. EPI 1: write bf16 hi/lo pair into g_Mh/g_Ml (splitm folded).
template <int EPI>
__global__ void __launch_bounds__(256, 1) mgemm(
    const float* __restrict__ A, const float* __restrict__ B, float* __restrict__ C,
    int K, int lda, int ldb, long sA, long sB, long sC)
{
    __shared__ __align__(16) u16 Ah[128][40], Al[128][40];
    __shared__ __align__(16) u16 Bh[128][40], Bl[128][40];
    int tid = threadIdx.x, lane = tid & 31, wid = tid >> 5;
    int wm = wid >> 2, wn = wid & 3;
    int bx = blockIdx.x, by = blockIdx.y, b = blockIdx.z;
    const float* Ab = A + (size_t)b * sA + (size_t)(by * 128) * lda;
    const float* Bb = B + (size_t)b * sB;
    float acc[4][4][4] = {};
    float4 va[4], vb[4];
    int arow = tid >> 1, acb = (tid & 1) * 16;
    auto LDG = [&](int k0) {
#pragma unroll
        for (int j = 0; j < 4; j++) {
            va[j] = *(const float4*)(Ab + (size_t)arow * lda + k0 + acb + 4 * j);
            vb[j] = *(const float4*)(Bb + (size_t)(bx * 128 + arow) * ldb + k0 + acb + 4 * j);
        }
    };
    auto STS = [&]() {
#pragma unroll
        for (int j = 0; j < 4; j++) {
            uint2 h, l;
            cvt4(va[j], h, l);
            *(uint2*)&Ah[arow][acb + 4 * j] = h;
            *(uint2*)&Al[arow][acb + 4 * j] = l;
            cvt4(vb[j], h, l);
            *(uint2*)&Bh[arow][acb + 4 * j] = h;
            *(uint2*)&Bl[arow][acb + 4 * j] = l;
        }
    };
    int T = K >> 5;
    LDG(0);
    for (int t = 0; t < T; t++) {
        STS();
        __syncthreads();
        if (t + 1 < T) LDG((t + 1) << 5);
#pragma unroll
        for (int kc = 0; kc < 32; kc += 16) {
            int kk = kc + (lane & 3) * 2;
            u32 afh[4][4], afl[4][4], bfh[4][2], bfl[4][2];
#pragma unroll
            for (int mf = 0; mf < 4; mf++) {
                int r0 = wm * 64 + mf * 16 + (lane >> 2);
                afh[mf][0] = *(const u32*)&Ah[r0][kk];
                afh[mf][1] = *(const u32*)&Ah[r0 + 8][kk];
                afh[mf][2] = *(const u32*)&Ah[r0][kk + 8];
                afh[mf][3] = *(const u32*)&Ah[r0 + 8][kk + 8];
                afl[mf][0] = *(const u32*)&Al[r0][kk];
                afl[mf][1] = *(const u32*)&Al[r0 + 8][kk];
                afl[mf][2] = *(const u32*)&Al[r0][kk + 8];
                afl[mf][3] = *(const u32*)&Al[r0 + 8][kk + 8];
            }
#pragma unroll
            for (int nf = 0; nf < 4; nf++) {
                int c0 = wn * 32 + nf * 8 + (lane >> 2);
                bfh[nf][0] = *(const u32*)&Bh[c0][kk];
                bfh[nf][1] = *(const u32*)&Bh[c0][kk + 8];
                bfl[nf][0] = *(const u32*)&Bl[c0][kk];
                bfl[nf][1] = *(const u32*)&Bl[c0][kk + 8];
            }
#pragma unroll
            for (int mf = 0; mf < 4; mf++)
#pragma unroll
                for (int nf = 0; nf < 4; nf++) {
                    mma16816(acc[mf][nf], afh[mf], bfh[nf]);
                    mma16816(acc[mf][nf], afh[mf], bfl[nf]);
                    mma16816(acc[mf][nf], afl[mf], bfh[nf]);
                }
        }
        __syncthreads();
    }
#pragma unroll
    for (int mf = 0; mf < 4; mf++) {
        int rg = by * 128 + wm * 64 + mf * 16 + (lane >> 2);
#pragma unroll
        for (int nf = 0; nf < 4; nf++) {
            int cg = bx * 128 + wn * 32 + nf * 8 + (lane & 3) * 2;
            float* a = acc[mf][nf];
            if (EPI == 0) {
                float* p = C + (size_t)b * sC + (size_t)rg * CC + cg;
                *(float2*)p = make_float2(a[0], a[1]);
                *(float2*)(p + 8 * CC) = make_float2(a[2], a[3]);
            } else {
                size_t i0 = (size_t)b * CC * CC + (size_t)rg * CC + cg;
                size_t i1 = i0 + 8 * CC;
                bf16 h0, l0, h1, l1;
                split2(a[0], h0, l0); split2(a[1], h1, l1);
                *(u32*)&g_Mh[i0] = pack2(h0, h1);
                *(u32*)&g_Ml[i0] = pack2(l0, l1);
                split2(a[2], h0, l0); split2(a[3], h1, l1);
                *(u32*)&g_Mh[i1] = pack2(h0, h1);
                *(u32*)&g_Ml[i1] = pack2(l0, l1);
            }
        }
    }
}

// ---------------- split x -> yh/yl and row-sum partials ---------------------
__global__ void splitx_kernel(const float* __restrict__ x) {
    int b = blockIdx.z, c0 = blockIdx.y * 32, n0 = blockIdx.x * 32;
    int tid = threadIdx.x;
    int c = tid >> 3, n4 = (tid & 7) * 4;
    float4 v = *(const float4*)(x + ((size_t)(b * CC + c0 + c)) * NPIX + n0 + n4);
    bf16 h[4], l[4];
    split2(v.x, h[0], l[0]); split2(v.y, h[1], l[1]);
    split2(v.z, h[2], l[2]); split2(v.w, h[3], l[3]);
    size_t yo = ((size_t)(b * CC + c0 + c)) * NPIX + n0 + n4;
    *(uint2*)(g_yh + yo) = make_uint2(pack2(h[0], h[1]), pack2(h[2], h[3]));
    *(uint2*)(g_yl + yo) = make_uint2(pack2(l[0], l[1]), pack2(l[2], l[3]));
    float ps = (v.x + v.y) + (v.z + v.w);
#pragma unroll
    for (int o = 4; o; o >>= 1) ps += __shfl_down_sync(0xFFFFFFFFu, ps, o, 8);
    if ((tid & 7) == 0)
        g_sxp[(size_t)(b * CC + c0 + c) * 128 + blockIdx.x] = ps;
}

// ---------------- reduce row-sum partials: warp per row ---------------------
__global__ void reduce_sx_kernel() {
    int row = blockIdx.x * 8 + (threadIdx.x >> 5);
    int lane = threadIdx.x & 31;
    const float* p = g_sxp + (size_t)row * 128;
    float s = 0.f;
#pragma unroll
    for (int j = 0; j < 4; j++) s += p[lane + 32 * j];
#pragma unroll
    for (int o = 16; o; o >>= 1) s += __shfl_down_sync(0xFFFFFFFFu, s, o);
    if (lane == 0) g_sx[row] = s;
}

// ---------------- qs/ks: warp per output, grid-parallel ---------------------
__global__ void proj_sums(const float* __restrict__ wq, const float* __restrict__ wk) {
    __shared__ float sxs[CC];
    int b = blockIdx.x, mat = blockIdx.y, zc = blockIdx.z;
    int tid = threadIdx.x, lane = tid & 31, wid = tid >> 5;
    sxs[tid] = g_sx[b * CC + tid];
    __syncthreads();
    const float* w = mat ? wk : wq;
    float* outv = mat ? g_ks : g_qs;
#pragma unroll
    for (int i = 0; i < 4; i++) {
        int o = zc * 32 + wid * 4 + i;
        const float* r = w + o * CC;
        float s = 0.f;
#pragma unroll
        for (int j = 0; j < 8; j++) {
            int cidx = lane + 32 * j;
            s += r[cidx] * sxs[cidx];
        }
#pragma unroll
        for (int off = 16; off; off >>= 1) s += __shfl_down_sync(0xFFFFFFFFu, s, off);
        if (lane == 0) outv[b * CC + o] = s;
    }
}

// ---------------- softmax (+ folded cv = A bv), warp-shuffle ----------------
__global__ void softmax_kernel(const float* __restrict__ bq, const float* __restrict__ bk,
                               const float* __restrict__ bv) {
    int row = blockIdx.x;
    int b = row >> 8, c = row & 255;
    int d = threadIdx.x, lane = d & 31, wid = d >> 5;
    __shared__ float sm[8], sm2[8], sm3[8];
    float v = g_L[(size_t)row * CC + d];
    float bqc = bq[c];
    v += g_qs[b * CC + c] * bk[d] + bqc * g_ks[b * CC + d] + 4096.f * bqc * bk[d];
    v *= 0.0625f;
    float wmx = v;
#pragma unroll
    for (int o = 16; o; o >>= 1) wmx = fmaxf(wmx, __shfl_xor_sync(0xFFFFFFFFu, wmx, o));
    if (lane == 0) sm[wid] = wmx;
    __syncthreads();
    float m = sm[0];
#pragma unroll
    for (int i = 1; i < 8; i++) m = fmaxf(m, sm[i]);
    float e = __expf(v - m);
    float ws = e;
#pragma unroll
    for (int o = 16; o; o >>= 1) ws += __shfl_xor_sync(0xFFFFFFFFu, ws, o);
    if (lane == 0) sm2[wid] = ws;
    __syncthreads();
    float s = sm2[0];
#pragma unroll
    for (int i = 1; i < 8; i++) s += sm2[i];
    float p = e * (1.0f / s);
    g_L[(size_t)row * CC + d] = p;
    float cvp = p * bv[d];
#pragma unroll
    for (int o = 16; o; o >>= 1) cvp += __shfl_xor_sync(0xFFFFFFFFu, cvp, o);
    if (lane == 0) sm3[wid] = cvp;
    __syncthreads();
    if (d == 0) {
        float cs = sm3[0];
#pragma unroll
        for (int i = 1; i < 8; i++) cs += sm3[i];
        g_cv[row] = cs;
    }
}

// ---------------- misc small kernels ----------------------------------------
__global__ void wvt_kernel(const float* __restrict__ wv) {
    int d = blockIdx.x, e = threadIdx.x;
    g_Wvt[e * CC + d] = wv[d * CC + e];
}
__global__ void reduceg_kernel() {
    int i = (blockIdx.x * 256 + threadIdx.x) * 4;
    float4 a = *(const float4*)(g_Gp + i);
    float4 b = *(const float4*)(g_Gp + (size_t)BB * CC * CC + i);
    float4 c = *(const float4*)(g_Gp + (size_t)2 * BB * CC * CC + i);
    *(float4*)(g_G + i) = make_float4(a.x + b.x + c.x, a.y + b.y + c.y,
                                      a.z + b.z + c.z, a.w + b.w + c.w);
}
// mirror: G[b][c][128+j] = G[b][128+j][c]  (fills the skipped (0,1) tile)
__global__ void mirror_kernel() {
    __shared__ float s[32][33];
    int b = blockIdx.z;
    int r0 = 128 + blockIdx.y * 32;
    int c0 = blockIdx.x * 32;
    float* Gb = g_G + (size_t)b * CC * CC;
    int tx = threadIdx.x & 31, ty = threadIdx.x >> 5;
#pragma unroll
    for (int i = ty; i < 32; i += 8)
        s[i][tx] = Gb[(size_t)(r0 + i) * CC + c0 + tx];
    __syncthreads();
#pragma unroll
    for (int i = ty; i < 32; i += 8)
        Gb[(size_t)(c0 + i) * CC + r0 + tx] = s[tx][i];
}

// ---------------- launcher ----------------
extern "C" void kernel_launch(void* const* d_in, const int* in_sizes, int n_in,
                              void* d_out, int out_size) {
    const float* x  = (const float*)d_in[0];
    const float* wq = (const float*)d_in[1];
    const float* bq = (const float*)d_in[2];
    const float* wk = (const float*)d_in[3];
    const float* bk = (const float*)d_in[4];
    const float* wv = (const float*)d_in[5];
    const float* bv = (const float*)d_in[6];
    float* out = (float*)d_out;

    float *pG, *pGp, *pT, *pL, *pWvt, *pcv;
    bf16 *pyh, *pyl, *pMh, *pMl;
    cudaGetSymbolAddress((void**)&pG, g_G);
    cudaGetSymbolAddress((void**)&pGp, g_Gp);
    cudaGetSymbolAddress((void**)&pT, g_T);
    cudaGetSymbolAddress((void**)&pL, g_L);
    cudaGetSymbolAddress((void**)&pWvt, g_Wvt);
    cudaGetSymbolAddress((void**)&pcv, g_cv);
    cudaGetSymbolAddress((void**)&pyh, g_yh);
    cudaGetSymbolAddress((void**)&pyl, g_yl);
    cudaGetSymbolAddress((void**)&pMh, g_Mh);
    cudaGetSymbolAddress((void**)&pMl, g_Ml);

    const int SMEMB0 = 2 * 20480 * 2;   // G path: 81920 B
    const int SMEMB1 = 2 * 18944 * 2;   // stage C path: 75776 B
    cudaFuncSetAttribute((const void*)bgemm<0, 1, 0>, cudaFuncAttributeMaxDynamicSharedMemorySize, SMEMB0);
    cudaFuncSetAttribute((const void*)bgemm<1, 0, 1>, cudaFuncAttributeMaxDynamicSharedMemorySize, SMEMB1);

    const long CN = (long)CC * NPIX;
    const long C2 = (long)CC * CC;

    splitx_kernel<<<dim3(128, 8, 16), 256>>>(x);
    reduce_sx_kernel<<<512, 256>>>();
    wvt_kernel<<<256, 256>>>(wv);
    proj_sums<<<dim3(16, 2, 8), 256>>>(wq, wk);
    // G partials: y y^T bf16, symmetric triangle tiles x split-K 3
    bgemm<0, 1, 0><<<dim3(3, 3, 16), 256, SMEMB0>>>(pyh, pyl, pyh, pyl, pGp,
                                                    0, NPIX, NPIX, CN, CN, C2, 0, 0, 0,
                                                    nullptr, nullptr);
    reduceg_kernel<<<1024, 256>>>();
    mirror_kernel<<<dim3(4, 4, 16), 256>>>();
    // T = Wq G ; L = T Wk^T ; softmax(+cv) ; M = A Wv^T (bf16 epilogue)
    mgemm<0><<<dim3(2, 2, 16), 256>>>(wq, pG, pT, CC, CC, CC, 0, C2, C2);
    mgemm<0><<<dim3(2, 2, 16), 256>>>(pT, wk, pL, CC, CC, CC, C2, 0, C2);
    softmax_kernel<<<4096, 256>>>(bq, bk, bv);
    mgemm<1><<<dim3(2, 2, 16), 256>>>(pL, pWvt, nullptr, CC, CC, CC, C2, 0, 0);
    // out = x + M x + cv  (A = M hi/lo [c][d], B = y hi/lo [d][n], T = 8)
    bgemm<1, 0, 1><<<dim3(32, 2, 16), 256, SMEMB1>>>(pMh, pMl, pyh, pyl, nullptr,
                                                     8, CC, NPIX, C2, CN, 0, 255, 8, 0,
                                                     pcv, out);
}